// round 9
// baseline (speedup 1.0000x reference)
#include <cuda_runtime.h>
#include <cuda_bf16.h>
#include <cstdint>

#define N_NODES  50000
#define N_EDGES  800000
#define N_GRAPHS 512
#define IN_C     128
#define HID      256
#define OUT_C    16

#define MPAD  50048            // N_NODES rounded to 128
#define MBLK  (MPAD / 128)     // 391

// ---------------- scratch (static device globals; no allocation) -------------
__device__ float g_agg [(size_t)MPAD * HID];   // A-fragment layout
__device__ float g_tmp [(size_t)MPAD * HID];   // A-fragment layout
__device__ float g_h   [(size_t)N_NODES * HID]; // row-major
__device__ float g_pool[N_GRAPHS * HID];
// B-fragment tf32 weights (incl. 4-word pads per 20-word lane group)
// sizes (words): m0: 2*16*1280=40960 ; m1..m5: 2*32*1280=81920
#define WT_TOTAL (40960 + 5 * 81920)
__device__ float g_wt [WT_TOTAL];
__device__ int   g_deg   [N_NODES];
__device__ int   g_rowptr[N_NODES + 1];
__device__ int   g_cursor[N_NODES];
__device__ int   g_csr   [N_EDGES];
__device__ int   g_gstart[N_GRAPHS + 1];

// ---------------- helpers -----------------------------------------------------
__device__ __forceinline__ int detect64(const void* ei) {
    const unsigned int* w = (const unsigned int*)ei;
    return ((w[1] | w[3] | w[5] | w[7]) == 0u) ? 1 : 0;
}
__device__ __forceinline__ int idx_at(const void* p, long long i, int is64) {
    if (is64) return (int)((const long long*)p)[i];
    return ((const int*)p)[i];
}
__device__ __forceinline__ uint32_t f2tf32(float f) {
    uint32_t r;
    asm("cvt.rna.tf32.f32 %0, %1;" : "=r"(r) : "f"(f));
    return r;
}
__device__ __forceinline__ float rtf(float f) {
    return __uint_as_float(f2tf32(f));
}

// A-fragment word index for value (r, k) of a [Mpad x K] matrix.
// per 128-row block, per k8-slab: 1024 words = [mb 0..7][lane 0..31][c 0..3]
// lane = (r&7)*4 + (k&3); c = ((r>>3)&1) + 2*((k>>2)&1)
__device__ __forceinline__ size_t afrag_word(int r, int k, int K) {
    return (size_t)((r >> 7) * (K >> 3) + (k >> 3)) * 1024
         + (size_t)(((r >> 4) & 7) * 128 + ((r & 7) * 4 + (k & 3)) * 4
         + ((r >> 3) & 1) + 2 * ((k >> 2) & 1));
}
// B-fragment word index for value (n, k) of a [Npad x K] weight (W^T layout).
// per 128-col block, per k8-slab: 1280 words = [wnh 0..1][lane 0..31][20]
// within lane: nt*2 + reg (words 16..19 are pad)
__device__ __forceinline__ size_t bfrag_word(int n, int k, int K) {
    return (size_t)((n >> 7) * (K >> 3) + (k >> 3)) * 1280
         + (size_t)(((n >> 6) & 1) * 640 + ((n & 7) * 4 + (k & 3)) * 20
         + ((n >> 3) & 7) * 2 + ((k >> 2) & 1));
}

// ---------------- weight pre-convert into B-fragment tf32 ----------------------
__global__ void wconv(const float* __restrict__ w0, const float* __restrict__ w1,
                      const float* __restrict__ w2, const float* __restrict__ w3,
                      const float* __restrict__ w4, const float* __restrict__ w5,
                      float* __restrict__ dst) {
    int idx = blockIdx.x * blockDim.x + threadIdx.x;   // over source elements
    const int E0 = IN_C * HID;          // 32768
    const int E1 = HID * HID;           // 65536
    if (idx >= E0 + 5 * E1) return;
    const float* src; int base, K, o;
    if (idx < E0)                 { src = w0; base = 0;                  K = IN_C; o = idx; }
    else {
        int m = (idx - E0) / E1;  o = (idx - E0) % E1; K = HID;
        base = 40960 + m * 81920;
        src = (m == 0) ? w1 : (m == 1) ? w2 : (m == 2) ? w3 : (m == 3) ? w4 : w5;
    }
    int k = o >> 8, n = o & 255;        // src is [K][HID] row-major
    dst[base + bfrag_word(n, k, K)] = rtf(src[(size_t)k * HID + n]);
}

// ---------------- CSR build ----------------------------------------------------
__global__ void deg_hist(const void* __restrict__ ei, int* __restrict__ deg) {
    int is64 = detect64(ei);
    int e = blockIdx.x * blockDim.x + threadIdx.x;
    if (e >= N_EDGES) return;
    int d = idx_at(ei, (long long)N_EDGES + e, is64);
    atomicAdd(&deg[d], 1);
}

// single-block scan: 1024 threads x 49 contiguous elements
#define SCH 49
__global__ void scan_one(const int* __restrict__ deg,
                         int* __restrict__ rowptr, int* __restrict__ cursor) {
    __shared__ int s[1024];
    int t = threadIdx.x;
    int beg = t * SCH, end = min(beg + SCH, N_NODES);
    int sum = 0;
    for (int i = beg; i < end; i++) sum += deg[i];
    s[t] = sum; __syncthreads();
    for (int off = 1; off < 1024; off <<= 1) {
        int x = (t >= off) ? s[t - off] : 0;
        __syncthreads();
        s[t] += x;
        __syncthreads();
    }
    int run = s[t] - sum;               // exclusive prefix
    for (int i = beg; i < end; i++) {
        rowptr[i] = run; cursor[i] = run; run += deg[i];
    }
    if (t == 1023) rowptr[N_NODES] = N_EDGES;
}

__global__ void csr_fill(const void* __restrict__ ei, int* __restrict__ cursor,
                         int* __restrict__ csr) {
    int is64 = detect64(ei);
    int e = blockIdx.x * blockDim.x + threadIdx.x;
    if (e >= N_EDGES) return;
    int s = idx_at(ei, e, is64);
    int d = idx_at(ei, (long long)N_EDGES + e, is64);
    int p = atomicAdd(&cursor[d], 1);
    csr[p] = s;
}

// ---------------- aggregation -> A-fragment tf32 output ------------------------
// reads row-major h/x; writes agg in A-fragment layout (tf32-rounded).
__global__ void aggregate4(const float4* __restrict__ h4,
                           const int* __restrict__ rowptr,
                           const int* __restrict__ csr,
                           float* __restrict__ out,
                           int c4shift)            // log2(C/4): 5 or 6
{
    int c4 = 1 << c4shift;
    int sub  = threadIdx.x >> c4shift;
    int t    = threadIdx.x & (c4 - 1);
    int npb  = 256 >> c4shift;
    int node = blockIdx.x * npb + sub;
    if (node >= N_NODES) return;
    int K = c4 * 4;

    int beg = rowptr[node], end = rowptr[node + 1];
    float4 acc = h4[((size_t)node << c4shift) + t];
    int e = beg;
    for (; e + 4 <= end; e += 4) {
        int s0 = csr[e], s1 = csr[e + 1], s2 = csr[e + 2], s3 = csr[e + 3];
        float4 v0 = h4[((size_t)s0 << c4shift) + t];
        float4 v1 = h4[((size_t)s1 << c4shift) + t];
        float4 v2 = h4[((size_t)s2 << c4shift) + t];
        float4 v3 = h4[((size_t)s3 << c4shift) + t];
        acc.x += v0.x + v1.x + v2.x + v3.x;
        acc.y += v0.y + v1.y + v2.y + v3.y;
        acc.z += v0.z + v1.z + v2.z + v3.z;
        acc.w += v0.w + v1.w + v2.w + v3.w;
    }
    for (; e < end; e++) {
        float4 v = h4[((size_t)csr[e] << c4shift) + t];
        acc.x += v.x; acc.y += v.y; acc.z += v.z; acc.w += v.w;
    }
    size_t wb = afrag_word(node, t * 4, K);   // k&3==0 -> +4 per element
    out[wb]      = rtf(acc.x);
    out[wb + 4]  = rtf(acc.y);
    out[wb + 8]  = rtf(acc.z);
    out[wb + 12] = rtf(acc.w);
}

// ---------------- TF32 tensor GEMM on fragment-layout operands -----------------
// A: A-frag [MPAD x K] tf32. B: B-frag weights. C = relu(A@W + bias).
// mode 1: write C in A-frag layout (tf32-rounded) for the next GEMM.
// mode 0: write C row-major f32.
// 256 thr, 8 warps (4m x 2n), warp tile 32x64, BM=BN=128, BK=16, 2-stage cp.async.
#define GK 16
#define STG_A 2048              // words per stage, A (2 slabs x 1024)
#define STG_B 2560              // words per stage, B (2 slabs x 1280)
#define STG_W (STG_A + STG_B)   // 4608 words = 18KB

__global__ __launch_bounds__(256, 2)
void gemm_frag(const uint32_t* __restrict__ Af,
               const uint32_t* __restrict__ Bfw,
               const float* __restrict__ bias,
               float* __restrict__ C,
               int M, int K, int N, int mode)
{
    __shared__ __align__(16) uint32_t Sm[2 * STG_W];
    uint32_t smem_u32;
    asm("{ .reg .u64 tmp; cvta.to.shared.u64 tmp, %1; cvt.u32.u64 %0, tmp; }"
        : "=r"(smem_u32) : "l"(Sm));

    int bm = blockIdx.x * 128;
    int bn = blockIdx.y * 128;
    int tid  = threadIdx.x;
    int wid  = tid >> 5;
    int lane = tid & 31;
    int grp  = lane >> 2;
    int tig  = lane & 3;
    int wm = (wid & 3) * 32;
    int wn = (wid >> 2) * 64;
    int wnh = wid >> 2;

    const uint32_t* Abase = Af  + (size_t)blockIdx.x * (K >> 3) * 1024;
    const uint32_t* Bbase = Bfw + (size_t)blockIdx.y * (K >> 3) * 1280;

    float acc[2][8][4];
    #pragma unroll
    for (int i = 0; i < 2; i++)
        #pragma unroll
        for (int j = 0; j < 8; j++)
            #pragma unroll
            for (int r = 0; r < 4; r++) acc[i][j][r] = 0.f;

    auto cp_tile = [&](int k0, int buf) {
        uint32_t sa = smem_u32 + (uint32_t)buf * (STG_W * 4);
        const uint32_t* asrc = Abase + (size_t)(k0 >> 3) * 1024;
        #pragma unroll
        for (int i = 0; i < 2; i++) {
            int c = tid + i * 256;
            asm volatile("cp.async.cg.shared.global [%0], [%1], 16;"
                :: "r"(sa + (uint32_t)c * 16), "l"(asrc + (size_t)c * 4) : "memory");
        }
        uint32_t sb = sa + STG_A * 4;
        const uint32_t* bsrc = Bbase + (size_t)(k0 >> 3) * 1280;
        #pragma unroll
        for (int i = 0; i < 2; i++) {
            int c = tid + i * 256;
            asm volatile("cp.async.cg.shared.global [%0], [%1], 16;"
                :: "r"(sb + (uint32_t)c * 16), "l"(bsrc + (size_t)c * 4) : "memory");
        }
        if (tid < 128) {
            int c = tid + 512;
            asm volatile("cp.async.cg.shared.global [%0], [%1], 16;"
                :: "r"(sb + (uint32_t)c * 16), "l"(bsrc + (size_t)c * 4) : "memory");
        }
        asm volatile("cp.async.commit_group;" ::: "memory");
    };

    cp_tile(0, 0);
    int niter = K / GK;

    for (int it = 0; it < niter; it++) {
        asm volatile("cp.async.wait_group 0;" ::: "memory");
        __syncthreads();
        if (it + 1 < niter) cp_tile((it + 1) * GK, (it + 1) & 1);

        const uint32_t* Asm = Sm + (it & 1) * STG_W;
        const uint32_t* Bsm = Asm + STG_A;

        #pragma unroll
        for (int ks = 0; ks < 2; ks++) {
            uint32_t af[2][4];
            #pragma unroll
            for (int mt = 0; mt < 2; mt++) {
                uint4 v = *(const uint4*)(Asm + ks * 1024
                                          + ((wm >> 4) + mt) * 128 + lane * 4);
                af[mt][0] = v.x; af[mt][1] = v.y; af[mt][2] = v.z; af[mt][3] = v.w;
            }
            const uint32_t* bp = Bsm + ks * 1280 + wnh * 640 + lane * 20;
            uint4 t0 = *(const uint4*)(bp);
            uint4 t1 = *(const uint4*)(bp + 4);
            uint4 t2 = *(const uint4*)(bp + 8);
            uint4 t3 = *(const uint4*)(bp + 12);
            uint32_t bf[8][2] = {{t0.x, t0.y}, {t0.z, t0.w}, {t1.x, t1.y}, {t1.z, t1.w},
                                 {t2.x, t2.y}, {t2.z, t2.w}, {t3.x, t3.y}, {t3.z, t3.w}};
            #pragma unroll
            for (int mt = 0; mt < 2; mt++)
                #pragma unroll
                for (int nt = 0; nt < 8; nt++) {
                    asm volatile(
                        "mma.sync.aligned.m16n8k8.row.col.f32.tf32.tf32.f32 "
                        "{%0,%1,%2,%3}, {%4,%5,%6,%7}, {%8,%9}, {%0,%1,%2,%3};"
                        : "+f"(acc[mt][nt][0]), "+f"(acc[mt][nt][1]),
                          "+f"(acc[mt][nt][2]), "+f"(acc[mt][nt][3])
                        : "r"(af[mt][0]), "r"(af[mt][1]),
                          "r"(af[mt][2]), "r"(af[mt][3]),
                          "r"(bf[nt][0]), "r"(bf[nt][1]));
                }
        }
        __syncthreads();
    }

    // epilogue
    #pragma unroll
    for (int mt = 0; mt < 2; mt++) {
        #pragma unroll
        for (int nt = 0; nt < 8; nt++) {
            int col = bn + wn + nt * 8 + 2 * tig;
            float b0 = bias[col], b1 = bias[col + 1];
            int r0 = bm + wm + mt * 16 + grp;
            float v00 = fmaxf(acc[mt][nt][0] + b0, 0.f);
            float v01 = fmaxf(acc[mt][nt][1] + b1, 0.f);
            float v10 = fmaxf(acc[mt][nt][2] + b0, 0.f);
            float v11 = fmaxf(acc[mt][nt][3] + b1, 0.f);
            if (mode) {        // A-frag tf32 output (feeds next GEMM, K' = N)
                if (r0 < M) {
                    C[afrag_word(r0, col, N)]     = rtf(v00);
                    C[afrag_word(r0, col + 1, N)] = rtf(v01);
                }
                if (r0 + 8 < M) {
                    C[afrag_word(r0 + 8, col, N)]     = rtf(v10);
                    C[afrag_word(r0 + 8, col + 1, N)] = rtf(v11);
                }
            } else {           // row-major f32
                if (r0 < M)
                    *(float2*)(C + (size_t)r0 * N + col) = make_float2(v00, v01);
                if (r0 + 8 < M)
                    *(float2*)(C + (size_t)(r0 + 8) * N + col) = make_float2(v10, v11);
            }
        }
    }
}

// ---------------- pooling over sorted batch -----------------------------------
__global__ void graph_bounds(const void* __restrict__ batch,
                             const void* __restrict__ ei,
                             int* __restrict__ gstart) {
    int is64 = detect64(ei);
    int g = blockIdx.x * blockDim.x + threadIdx.x;
    if (g > N_GRAPHS) return;
    int lo = 0, hi = N_NODES;
    while (lo < hi) {
        int mid = (lo + hi) >> 1;
        if (idx_at(batch, mid, is64) < g) lo = mid + 1; else hi = mid;
    }
    gstart[g] = lo;
}

__global__ void pool_mean(const float* __restrict__ h,
                          const int* __restrict__ gstart,
                          float* __restrict__ pooled) {
    int g = blockIdx.x;
    int t = threadIdx.x;           // HID threads
    int beg = gstart[g], end = gstart[g + 1];
    float acc = 0.f;
    int n = beg;
    for (; n + 4 <= end; n += 4) {
        float a0 = h[(size_t)(n + 0) * HID + t];
        float a1 = h[(size_t)(n + 1) * HID + t];
        float a2 = h[(size_t)(n + 2) * HID + t];
        float a3 = h[(size_t)(n + 3) * HID + t];
        acc += a0 + a1 + a2 + a3;
    }
    for (; n < end; n++) acc += h[(size_t)n * HID + t];
    float c = fmaxf((float)(end - beg), 1.0f);
    pooled[(size_t)g * HID + t] = acc / c;
}

// ---------------- final MLP: out = relu(pooled@W1+b1)@W2+b2 ------------------
__global__ void final_mlp(const float* __restrict__ pooled,
                          const float* __restrict__ w1, const float* __restrict__ b1,
                          const float* __restrict__ w2, const float* __restrict__ b2,
                          float* __restrict__ out) {
    __shared__ float p[HID];
    __shared__ float hh[HID];
    int g = blockIdx.x;
    int t = threadIdx.x;

    p[t] = pooled[(size_t)g * HID + t];
    __syncthreads();

    float acc = b1[t];
    #pragma unroll 8
    for (int k = 0; k < HID; k++)
        acc += p[k] * w1[(size_t)k * HID + t];
    hh[t] = fmaxf(acc, 0.f);
    __syncthreads();

    int o  = t >> 4;
    int kk = t & 15;
    float s = 0.f;
    for (int k = kk; k < HID; k += 16)
        s += hh[k] * w2[(size_t)k * OUT_C + o];
    #pragma unroll
    for (int off = 8; off; off >>= 1)
        s += __shfl_xor_sync(0xffffffffu, s, off);
    if (kk == 0) out[(size_t)g * OUT_C + o] = s + b2[o];
}

// ---------------- launcher ----------------------------------------------------
extern "C" void kernel_launch(void* const* d_in, const int* in_sizes, int n_in,
                              void* d_out, int out_size)
{
    const float* x     = (const float*)d_in[0];
    const void*  ei    = d_in[1];
    const void*  batch = d_in[2];
    const float* w[16];
    for (int i = 0; i < 16; i++) w[i] = (const float*)d_in[3 + i];
    float* out = (float*)d_out;

    float *agg, *tmp, *h, *pool, *wt;
    int *deg, *rowptr, *cursor, *csr, *gstart;
    cudaGetSymbolAddress((void**)&agg,    g_agg);
    cudaGetSymbolAddress((void**)&tmp,    g_tmp);
    cudaGetSymbolAddress((void**)&h,      g_h);
    cudaGetSymbolAddress((void**)&pool,   g_pool);
    cudaGetSymbolAddress((void**)&wt,     g_wt);
    cudaGetSymbolAddress((void**)&deg,    g_deg);
    cudaGetSymbolAddress((void**)&rowptr, g_rowptr);
    cudaGetSymbolAddress((void**)&cursor, g_cursor);
    cudaGetSymbolAddress((void**)&csr,    g_csr);
    cudaGetSymbolAddress((void**)&gstart, g_gstart);

    // B-frag weight offsets in g_wt (words)
    const int wt_off[6] = {0, 40960, 122880, 204800, 286720, 368640};

    // ---- CSR build (once, reused by all 3 layers) ----
    cudaMemsetAsync(deg, 0, N_NODES * sizeof(int));
    deg_hist<<<(N_EDGES + 255) / 256, 256>>>(ei, deg);              // launch 0
    scan_one<<<1, 1024>>>(deg, rowptr, cursor);                     // launch 1
    csr_fill<<<(N_EDGES + 255) / 256, 256>>>(ei, cursor, csr);      // launch 2

    // ---- 3 GIN layers ----
    for (int layer = 0; layer < 3; layer++) {
        const float* hin = (layer == 0) ? x : h;
        int K = (layer == 0) ? IN_C : HID;
        int c4shift = (layer == 0) ? 5 : 6;
        int npb = 256 >> c4shift;

        aggregate4<<<(N_NODES + npb - 1) / npb, 256>>>(             // launch 3 (L0)
            (const float4*)hin, rowptr, csr, agg, c4shift);

        if (layer == 0)  // weight pre-convert (any point before first gemm)
            wconv<<<(IN_C * HID + 5 * HID * HID + 255) / 256, 256>>>(
                w[0], w[2], w[4], w[6], w[8], w[10], wt);

        dim3 grid(MBLK, HID / 128);
        // gemm1: frag output (feeds gemm2)
        gemm_frag<<<grid, 256>>>((const uint32_t*)agg,
                                 (const uint32_t*)(wt + wt_off[layer * 2 + 0]),
                                 w[layer * 4 + 1], tmp, N_NODES, K, HID, 1);
        // gemm2: row-major f32 output (feeds aggregate/pool)
        gemm_frag<<<grid, 256>>>((const uint32_t*)tmp,
                                 (const uint32_t*)(wt + wt_off[layer * 2 + 1]),
                                 w[layer * 4 + 3], h, N_NODES, HID, HID, 0);
    }

    // ---- pooling (batch is sorted) ----
    graph_bounds<<<3, 256>>>(batch, ei, gstart);
    pool_mean<<<N_GRAPHS, HID>>>(h, gstart, pool);

    final_mlp<<<N_GRAPHS, HID>>>(pool, w[12], w[13], w[14], w[15], out);
}

// round 10
// speedup vs baseline: 1.3613x; 1.3613x over previous
#include <cuda_runtime.h>
#include <cuda_bf16.h>
#include <cstdint>

#define N_NODES  50000
#define N_EDGES  800000
#define N_GRAPHS 512
#define IN_C     128
#define HID      256
#define OUT_C    16

// ---------------- scratch (static device globals; no allocation) -------------
__device__ float g_agg [(size_t)N_NODES * HID];
__device__ float g_tmp [(size_t)N_NODES * HID];
__device__ float g_h   [(size_t)N_NODES * HID];
__device__ float g_pool[N_GRAPHS * HID];
__device__ int   g_deg   [N_NODES];
__device__ int   g_rowptr[N_NODES + 1];
__device__ int   g_cursor[N_NODES];
__device__ int   g_csr   [N_EDGES];
__device__ int   g_gstart[N_GRAPHS + 1];

// ---------------- helpers -----------------------------------------------------
__device__ __forceinline__ int detect64(const void* ei) {
    const unsigned int* w = (const unsigned int*)ei;
    return ((w[1] | w[3] | w[5] | w[7]) == 0u) ? 1 : 0;
}
__device__ __forceinline__ int idx_at(const void* p, long long i, int is64) {
    if (is64) return (int)((const long long*)p)[i];
    return ((const int*)p)[i];
}
__device__ __forceinline__ uint32_t f2tf32(float f) {
    uint32_t r;
    asm("cvt.rna.tf32.f32 %0, %1;" : "=r"(r) : "f"(f));
    return r;
}

// ---------------- CSR build ----------------------------------------------------
__global__ void deg_hist(const void* __restrict__ ei, int* __restrict__ deg) {
    int is64 = detect64(ei);
    int e = blockIdx.x * blockDim.x + threadIdx.x;
    if (e >= N_EDGES) return;
    int d = idx_at(ei, (long long)N_EDGES + e, is64);
    atomicAdd(&deg[d], 1);
}

// single-block scan: 1024 threads x 49 contiguous elements each
#define SCH 49
__global__ void scan_one(const int* __restrict__ deg,
                         int* __restrict__ rowptr, int* __restrict__ cursor) {
    __shared__ int s[1024];
    int t = threadIdx.x;
    int beg = t * SCH, end = min(beg + SCH, N_NODES);
    int sum = 0;
    for (int i = beg; i < end; i++) sum += deg[i];
    s[t] = sum; __syncthreads();
    for (int off = 1; off < 1024; off <<= 1) {
        int x = (t >= off) ? s[t - off] : 0;
        __syncthreads();
        s[t] += x;
        __syncthreads();
    }
    int run = s[t] - sum;               // exclusive prefix
    for (int i = beg; i < end; i++) {
        rowptr[i] = run; cursor[i] = run; run += deg[i];
    }
    if (t == 1023) rowptr[N_NODES] = N_EDGES;
}

__global__ void csr_fill(const void* __restrict__ ei, int* __restrict__ cursor,
                         int* __restrict__ csr) {
    int is64 = detect64(ei);
    int e = blockIdx.x * blockDim.x + threadIdx.x;
    if (e >= N_EDGES) return;
    int s = idx_at(ei, e, is64);
    int d = idx_at(ei, (long long)N_EDGES + e, is64);
    int p = atomicAdd(&cursor[d], 1);
    csr[p] = s;
}

// ---------------- aggregation: out[i] = h[i] + sum_{j in N(i)} h[j] ----------
// (R5 form, templated shift) float4 lanes; C/4 threads per node.
template<int C4S>
__global__ void aggregate4(const float4* __restrict__ h4,
                           const int* __restrict__ rowptr,
                           const int* __restrict__ csr,
                           float4* __restrict__ out)
{
    constexpr int c4 = 1 << C4S;
    int sub  = threadIdx.x >> C4S;
    int t    = threadIdx.x & (c4 - 1);
    constexpr int npb = 256 >> C4S;
    int node = blockIdx.x * npb + sub;
    if (node >= N_NODES) return;

    const float4* ht = h4 + t;
    int beg = rowptr[node], end = rowptr[node + 1];
    float4 acc = ht[(size_t)node << C4S];
    int e = beg;
    for (; e + 4 <= end; e += 4) {
        int s0 = csr[e], s1 = csr[e + 1], s2 = csr[e + 2], s3 = csr[e + 3];
        float4 v0 = ht[(size_t)s0 << C4S];
        float4 v1 = ht[(size_t)s1 << C4S];
        float4 v2 = ht[(size_t)s2 << C4S];
        float4 v3 = ht[(size_t)s3 << C4S];
        acc.x += v0.x + v1.x + v2.x + v3.x;
        acc.y += v0.y + v1.y + v2.y + v3.y;
        acc.z += v0.z + v1.z + v2.z + v3.z;
        acc.w += v0.w + v1.w + v2.w + v3.w;
    }
    for (; e < end; e++) {
        float4 v = ht[(size_t)csr[e] << C4S];
        acc.x += v.x; acc.y += v.y; acc.z += v.z; acc.w += v.w;
    }
    out[((size_t)node << C4S) + t] = acc;
}

// ---------------- TF32 tensor-core GEMM: C = relu(A @ W + bias) ---------------
// R5 structure; A smem uses k-interleaved columns so fragment loads are LDS.64.
// col(k) = (k>>3)*8 + (k&3)*2 + ((k>>2)&1); ASTRIDE 40 -> conflict-free loads.
#define GBM 128
#define GBN 128
#define GBK 32
#define ASTRIDE 40
#define BSTRIDE 136

__global__ __launch_bounds__(256, 2)
void gemm_tf32(const float* __restrict__ A,
               const float* __restrict__ W,      // K x N row-major
               const float* __restrict__ bias,   // N
               float* __restrict__ C,
               int M, int K, int N)
{
    __shared__ __align__(16) uint32_t As[GBM][ASTRIDE];
    __shared__ uint32_t Bs[GBK][BSTRIDE];

    int bm = blockIdx.x * GBM;
    int bn = blockIdx.y * GBN;
    int tid  = threadIdx.x;
    int wid  = tid >> 5;
    int lane = tid & 31;
    int grp  = lane >> 2;     // 0..7
    int tig  = lane & 3;      // 0..3
    int wm = (wid & 3) * 32;  // warp row offset in tile
    int wn = (wid >> 2) * 64; // warp col offset in tile

    float acc[2][8][4];
    #pragma unroll
    for (int i = 0; i < 2; i++)
        #pragma unroll
        for (int j = 0; j < 8; j++)
            #pragma unroll
            for (int r = 0; r < 4; r++) acc[i][j][r] = 0.f;

    float4 pa[4], pb[4];

    auto ld_tiles = [&](int k0) {
        #pragma unroll
        for (int i = 0; i < 4; i++) {
            int li = tid + i * 256;
            int r  = li >> 3;          // 0..127
            int cq = (li & 7) * 4;     // 0..28
            int row = bm + r;
            pa[i] = (row < M) ? *(const float4*)(A + (size_t)row * K + k0 + cq)
                              : make_float4(0.f, 0.f, 0.f, 0.f);
        }
        #pragma unroll
        for (int i = 0; i < 4; i++) {
            int li = tid + i * 256;
            int kr = li >> 5;          // 0..31
            int cq = (li & 31) * 4;    // 0..124
            pb[i] = *(const float4*)(W + (size_t)(k0 + kr) * N + bn + cq);
        }
    };

    auto st_tiles = [&]() {
        #pragma unroll
        for (int i = 0; i < 4; i++) {
            int li = tid + i * 256;
            int r  = li >> 3;
            int kq = (li & 7) * 4;               // 0,4,8,...,28 (mult of 4)
            // col(k)= (k>>3)*8 + (k&3)*2 + ((k>>2)&1); k=kq+j, j=0..3
            int cb = (kq >> 3) * 8 + ((kq >> 2) & 1);
            As[r][cb + 0] = f2tf32(pa[i].x);
            As[r][cb + 2] = f2tf32(pa[i].y);
            As[r][cb + 4] = f2tf32(pa[i].z);
            As[r][cb + 6] = f2tf32(pa[i].w);
        }
        #pragma unroll
        for (int i = 0; i < 4; i++) {
            int li = tid + i * 256;
            int kr = li >> 5;
            int cq = (li & 31) * 4;
            Bs[kr][cq + 0] = f2tf32(pb[i].x);
            Bs[kr][cq + 1] = f2tf32(pb[i].y);
            Bs[kr][cq + 2] = f2tf32(pb[i].z);
            Bs[kr][cq + 3] = f2tf32(pb[i].w);
        }
    };

    ld_tiles(0);

    for (int k0 = 0; k0 < K; k0 += GBK) {
        st_tiles();
        __syncthreads();
        if (k0 + GBK < K) ld_tiles(k0 + GBK);   // hide LDG behind MMA phase

        #pragma unroll
        for (int ks = 0; ks < GBK; ks += 8) {
            // A fragments: LDS.64 pairs (k=tig, k=tig+4) are adjacent words
            uint2 ua[2][2];
            #pragma unroll
            for (int mt = 0; mt < 2; mt++) {
                int r0 = wm + mt * 16 + grp;
                ua[mt][0] = *(const uint2*)&As[r0][ks + tig * 2];
                ua[mt][1] = *(const uint2*)&As[r0 + 8][ks + tig * 2];
            }
            uint32_t bf[8][2];
            #pragma unroll
            for (int nt = 0; nt < 8; nt++) {
                int c0 = wn + nt * 8 + grp;
                bf[nt][0] = Bs[ks + tig][c0];
                bf[nt][1] = Bs[ks + tig + 4][c0];
            }
            #pragma unroll
            for (int mt = 0; mt < 2; mt++)
                #pragma unroll
                for (int nt = 0; nt < 8; nt++) {
                    asm volatile(
                        "mma.sync.aligned.m16n8k8.row.col.f32.tf32.tf32.f32 "
                        "{%0,%1,%2,%3}, {%4,%5,%6,%7}, {%8,%9}, {%0,%1,%2,%3};"
                        : "+f"(acc[mt][nt][0]), "+f"(acc[mt][nt][1]),
                          "+f"(acc[mt][nt][2]), "+f"(acc[mt][nt][3])
                        : "r"(ua[mt][0].x), "r"(ua[mt][1].x),
                          "r"(ua[mt][0].y), "r"(ua[mt][1].y),
                          "r"(bf[nt][0]), "r"(bf[nt][1]));
                }
        }
        __syncthreads();
    }

    // epilogue: bias + relu, float2 stores
    #pragma unroll
    for (int mt = 0; mt < 2; mt++) {
        #pragma unroll
        for (int nt = 0; nt < 8; nt++) {
            int col = bn + wn + nt * 8 + 2 * tig;
            float b0 = bias[col], b1 = bias[col + 1];
            int r0 = bm + wm + mt * 16 + grp;
            if (r0 < M) {
                float2 c;
                c.x = fmaxf(acc[mt][nt][0] + b0, 0.f);
                c.y = fmaxf(acc[mt][nt][1] + b1, 0.f);
                *(float2*)(C + (size_t)r0 * N + col) = c;
            }
            if (r0 + 8 < M) {
                float2 c;
                c.x = fmaxf(acc[mt][nt][2] + b0, 0.f);
                c.y = fmaxf(acc[mt][nt][3] + b1, 0.f);
                *(float2*)(C + (size_t)(r0 + 8) * N + col) = c;
            }
        }
    }
}

// ---------------- pooling over sorted batch -----------------------------------
__global__ void graph_bounds(const void* __restrict__ batch,
                             const void* __restrict__ ei,
                             int* __restrict__ gstart) {
    int is64 = detect64(ei);
    int g = blockIdx.x * blockDim.x + threadIdx.x;
    if (g > N_GRAPHS) return;
    int lo = 0, hi = N_NODES;
    while (lo < hi) {
        int mid = (lo + hi) >> 1;
        if (idx_at(batch, mid, is64) < g) lo = mid + 1; else hi = mid;
    }
    gstart[g] = lo;
}

__global__ void pool_mean(const float* __restrict__ h,
                          const int* __restrict__ gstart,
                          float* __restrict__ pooled) {
    int g = blockIdx.x;
    int t = threadIdx.x;           // HID threads
    int beg = gstart[g], end = gstart[g + 1];
    float acc = 0.f;
    int n = beg;
    for (; n + 4 <= end; n += 4) {
        float a0 = h[(size_t)(n + 0) * HID + t];
        float a1 = h[(size_t)(n + 1) * HID + t];
        float a2 = h[(size_t)(n + 2) * HID + t];
        float a3 = h[(size_t)(n + 3) * HID + t];
        acc += a0 + a1 + a2 + a3;
    }
    for (; n < end; n++) acc += h[(size_t)n * HID + t];
    float c = fmaxf((float)(end - beg), 1.0f);
    pooled[(size_t)g * HID + t] = acc / c;
}

// ---------------- final MLP: out = relu(pooled@W1+b1)@W2+b2 ------------------
__global__ void final_mlp(const float* __restrict__ pooled,
                          const float* __restrict__ w1, const float* __restrict__ b1,
                          const float* __restrict__ w2, const float* __restrict__ b2,
                          float* __restrict__ out) {
    __shared__ float p[HID];
    __shared__ float hh[HID];
    int g = blockIdx.x;
    int t = threadIdx.x;

    p[t] = pooled[(size_t)g * HID + t];
    __syncthreads();

    float acc = b1[t];
    #pragma unroll 8
    for (int k = 0; k < HID; k++)
        acc += p[k] * w1[(size_t)k * HID + t];
    hh[t] = fmaxf(acc, 0.f);
    __syncthreads();

    int o  = t >> 4;
    int kk = t & 15;
    float s = 0.f;
    for (int k = kk; k < HID; k += 16)
        s += hh[k] * w2[(size_t)k * OUT_C + o];
    #pragma unroll
    for (int off = 8; off; off >>= 1)
        s += __shfl_xor_sync(0xffffffffu, s, off);
    if (kk == 0) out[(size_t)g * OUT_C + o] = s + b2[o];
}

// ---------------- launcher ----------------------------------------------------
extern "C" void kernel_launch(void* const* d_in, const int* in_sizes, int n_in,
                              void* d_out, int out_size)
{
    const float* x     = (const float*)d_in[0];
    const void*  ei    = d_in[1];
    const void*  batch = d_in[2];
    const float* w[16];
    for (int i = 0; i < 16; i++) w[i] = (const float*)d_in[3 + i];
    float* out = (float*)d_out;

    float *agg, *tmp, *h, *pool;
    int *deg, *rowptr, *cursor, *csr, *gstart;
    cudaGetSymbolAddress((void**)&agg,    g_agg);
    cudaGetSymbolAddress((void**)&tmp,    g_tmp);
    cudaGetSymbolAddress((void**)&h,      g_h);
    cudaGetSymbolAddress((void**)&pool,   g_pool);
    cudaGetSymbolAddress((void**)&deg,    g_deg);
    cudaGetSymbolAddress((void**)&rowptr, g_rowptr);
    cudaGetSymbolAddress((void**)&cursor, g_cursor);
    cudaGetSymbolAddress((void**)&csr,    g_csr);
    cudaGetSymbolAddress((void**)&gstart, g_gstart);

    // ---- CSR build (once, reused by all 3 layers) ----
    cudaMemsetAsync(deg, 0, N_NODES * sizeof(int));
    deg_hist<<<(N_EDGES + 255) / 256, 256>>>(ei, deg);              // launch 0
    scan_one<<<1, 1024>>>(deg, rowptr, cursor);                     // launch 1
    csr_fill<<<(N_EDGES + 255) / 256, 256>>>(ei, cursor, csr);      // launch 2

    // ---- 3 GIN layers ----
    for (int layer = 0; layer < 3; layer++) {
        const float* hin = (layer == 0) ? x : h;
        int K = (layer == 0) ? IN_C : HID;

        if (layer == 0)
            aggregate4<5><<<(N_NODES * 32 + 255) / 256, 256>>>(     // launch 3
                (const float4*)hin, rowptr, csr, (float4*)agg);
        else
            aggregate4<6><<<(N_NODES * 64 + 255) / 256, 256>>>(
                (const float4*)hin, rowptr, csr, (float4*)agg);

        dim3 grid((N_NODES + GBM - 1) / GBM, HID / GBN);
        gemm_tf32<<<grid, 256>>>(agg, w[layer * 4 + 0], w[layer * 4 + 1],
                                 tmp, N_NODES, K, HID);
        gemm_tf32<<<grid, 256>>>(tmp, w[layer * 4 + 2], w[layer * 4 + 3],
                                 h, N_NODES, HID, HID);
    }

    // ---- pooling (batch is sorted) ----
    graph_bounds<<<3, 256>>>(batch, ei, gstart);
    pool_mean<<<N_GRAPHS, HID>>>(h, gstart, pool);

    final_mlp<<<N_GRAPHS, HID>>>(pool, w[12], w[13], w[14], w[15], out);
}

// round 11
// speedup vs baseline: 1.4865x; 1.0920x over previous
#include <cuda_runtime.h>
#include <cuda_bf16.h>
#include <cstdint>

#define N_NODES  50000
#define N_EDGES  800000
#define N_GRAPHS 512
#define IN_C     128
#define HID      256
#define OUT_C    16

// ---------------- scratch (static device globals; no allocation) -------------
__device__ float g_agg [(size_t)N_NODES * HID];
__device__ float g_tmp [(size_t)N_NODES * HID];
__device__ float g_h   [(size_t)N_NODES * HID];
__device__ float g_pool[N_GRAPHS * HID];
__device__ int   g_deg   [N_NODES];
__device__ int   g_rowptr[N_NODES + 1];
__device__ int   g_cursor[N_NODES];
__device__ int   g_csr   [N_EDGES];
__device__ int   g_gstart[N_GRAPHS + 1];

// ---------------- helpers -----------------------------------------------------
__device__ __forceinline__ int detect64(const void* ei) {
    const unsigned int* w = (const unsigned int*)ei;
    return ((w[1] | w[3] | w[5] | w[7]) == 0u) ? 1 : 0;
}
__device__ __forceinline__ int idx_at(const void* p, long long i, int is64) {
    if (is64) return (int)((const long long*)p)[i];
    return ((const int*)p)[i];
}
__device__ __forceinline__ uint32_t f2tf32(float f) {
    uint32_t r;
    asm("cvt.rna.tf32.f32 %0, %1;" : "=r"(r) : "f"(f));
    return r;
}

// ---------------- CSR build ----------------------------------------------------
__global__ void deg_hist(const void* __restrict__ ei, int* __restrict__ deg) {
    int is64 = detect64(ei);
    int e = blockIdx.x * blockDim.x + threadIdx.x;
    if (e >= N_EDGES) return;
    int d = idx_at(ei, (long long)N_EDGES + e, is64);
    atomicAdd(&deg[d], 1);
}

// single-block scan: 1024 threads x 49 contiguous elements each
#define SCH 49
__global__ void scan_one(const int* __restrict__ deg,
                         int* __restrict__ rowptr, int* __restrict__ cursor) {
    __shared__ int s[1024];
    int t = threadIdx.x;
    int beg = t * SCH, end = min(beg + SCH, N_NODES);
    int sum = 0;
    for (int i = beg; i < end; i++) sum += deg[i];
    s[t] = sum; __syncthreads();
    for (int off = 1; off < 1024; off <<= 1) {
        int x = (t >= off) ? s[t - off] : 0;
        __syncthreads();
        s[t] += x;
        __syncthreads();
    }
    int run = s[t] - sum;               // exclusive prefix
    for (int i = beg; i < end; i++) {
        rowptr[i] = run; cursor[i] = run; run += deg[i];
    }
    if (t == 1023) rowptr[N_NODES] = N_EDGES;
}

__global__ void csr_fill(const void* __restrict__ ei, int* __restrict__ cursor,
                         int* __restrict__ csr) {
    int is64 = detect64(ei);
    int e = blockIdx.x * blockDim.x + threadIdx.x;
    if (e >= N_EDGES) return;
    int s = idx_at(ei, e, is64);
    int d = idx_at(ei, (long long)N_EDGES + e, is64);
    int p = atomicAdd(&cursor[d], 1);
    csr[p] = s;
}

// ---------------- aggregation: out[i] = h[i] + sum_{j in N(i)} h[j] ----------
// (exact R5 form - measured best) float4 lanes; C/4 threads per node.
__global__ void aggregate4(const float4* __restrict__ h4,
                           const int* __restrict__ rowptr,
                           const int* __restrict__ csr,
                           float4* __restrict__ out,
                           int c4shift)            // log2(C/4): 5 or 6
{
    int c4 = 1 << c4shift;
    int sub  = threadIdx.x >> c4shift;
    int t    = threadIdx.x & (c4 - 1);
    int npb  = 256 >> c4shift;
    int node = blockIdx.x * npb + sub;
    if (node >= N_NODES) return;

    int beg = rowptr[node], end = rowptr[node + 1];
    float4 acc = h4[((size_t)node << c4shift) + t];
    int e = beg;
    for (; e + 4 <= end; e += 4) {
        int s0 = csr[e], s1 = csr[e + 1], s2 = csr[e + 2], s3 = csr[e + 3];
        float4 v0 = h4[((size_t)s0 << c4shift) + t];
        float4 v1 = h4[((size_t)s1 << c4shift) + t];
        float4 v2 = h4[((size_t)s2 << c4shift) + t];
        float4 v3 = h4[((size_t)s3 << c4shift) + t];
        acc.x += v0.x + v1.x + v2.x + v3.x;
        acc.y += v0.y + v1.y + v2.y + v3.y;
        acc.z += v0.z + v1.z + v2.z + v3.z;
        acc.w += v0.w + v1.w + v2.w + v3.w;
    }
    for (; e < end; e++) {
        float4 v = h4[((size_t)csr[e] << c4shift) + t];
        acc.x += v.x; acc.y += v.y; acc.z += v.z; acc.w += v.w;
    }
    out[((size_t)node << c4shift) + t] = acc;
}

// ---------------- TF32 tensor-core GEMM (exact R5 form - measured best) -------
#define GBM 128
#define GBN 128
#define GBK 32
#define ASTRIDE 36
#define BSTRIDE 136

__global__ __launch_bounds__(256, 2)
void gemm_tf32(const float* __restrict__ A,
               const float* __restrict__ W,      // K x N row-major
               const float* __restrict__ bias,   // N
               float* __restrict__ C,
               int M, int K, int N)
{
    __shared__ uint32_t As[GBM][ASTRIDE];
    __shared__ uint32_t Bs[GBK][BSTRIDE];

    int bm = blockIdx.x * GBM;
    int bn = blockIdx.y * GBN;
    int tid  = threadIdx.x;
    int wid  = tid >> 5;
    int lane = tid & 31;
    int grp  = lane >> 2;     // 0..7
    int tig  = lane & 3;      // 0..3
    int wm = (wid & 3) * 32;  // warp row offset in tile
    int wn = (wid >> 2) * 64; // warp col offset in tile

    float acc[2][8][4];
    #pragma unroll
    for (int i = 0; i < 2; i++)
        #pragma unroll
        for (int j = 0; j < 8; j++)
            #pragma unroll
            for (int r = 0; r < 4; r++) acc[i][j][r] = 0.f;

    float4 pa[4], pb[4];

    auto ld_tiles = [&](int k0) {
        #pragma unroll
        for (int i = 0; i < 4; i++) {
            int li = tid + i * 256;
            int r  = li >> 3;          // 0..127
            int cq = (li & 7) * 4;     // 0..28
            int row = bm + r;
            pa[i] = (row < M) ? *(const float4*)(A + (size_t)row * K + k0 + cq)
                              : make_float4(0.f, 0.f, 0.f, 0.f);
        }
        #pragma unroll
        for (int i = 0; i < 4; i++) {
            int li = tid + i * 256;
            int kr = li >> 5;          // 0..31
            int cq = (li & 31) * 4;    // 0..124
            pb[i] = *(const float4*)(W + (size_t)(k0 + kr) * N + bn + cq);
        }
    };

    auto st_tiles = [&]() {
        #pragma unroll
        for (int i = 0; i < 4; i++) {
            int li = tid + i * 256;
            int r  = li >> 3;
            int cq = (li & 7) * 4;
            As[r][cq + 0] = f2tf32(pa[i].x);
            As[r][cq + 1] = f2tf32(pa[i].y);
            As[r][cq + 2] = f2tf32(pa[i].z);
            As[r][cq + 3] = f2tf32(pa[i].w);
        }
        #pragma unroll
        for (int i = 0; i < 4; i++) {
            int li = tid + i * 256;
            int kr = li >> 5;
            int cq = (li & 31) * 4;
            Bs[kr][cq + 0] = f2tf32(pb[i].x);
            Bs[kr][cq + 1] = f2tf32(pb[i].y);
            Bs[kr][cq + 2] = f2tf32(pb[i].z);
            Bs[kr][cq + 3] = f2tf32(pb[i].w);
        }
    };

    ld_tiles(0);

    for (int k0 = 0; k0 < K; k0 += GBK) {
        st_tiles();
        __syncthreads();
        if (k0 + GBK < K) ld_tiles(k0 + GBK);   // hide LDG behind MMA phase

        #pragma unroll
        for (int ks = 0; ks < GBK; ks += 8) {
            uint32_t af[2][4];
            #pragma unroll
            for (int mt = 0; mt < 2; mt++) {
                int r0 = wm + mt * 16 + grp;
                af[mt][0] = As[r0][ks + tig];
                af[mt][1] = As[r0 + 8][ks + tig];
                af[mt][2] = As[r0][ks + tig + 4];
                af[mt][3] = As[r0 + 8][ks + tig + 4];
            }
            uint32_t bf[8][2];
            #pragma unroll
            for (int nt = 0; nt < 8; nt++) {
                int c0 = wn + nt * 8 + grp;
                bf[nt][0] = Bs[ks + tig][c0];
                bf[nt][1] = Bs[ks + tig + 4][c0];
            }
            #pragma unroll
            for (int mt = 0; mt < 2; mt++)
                #pragma unroll
                for (int nt = 0; nt < 8; nt++) {
                    asm volatile(
                        "mma.sync.aligned.m16n8k8.row.col.f32.tf32.tf32.f32 "
                        "{%0,%1,%2,%3}, {%4,%5,%6,%7}, {%8,%9}, {%0,%1,%2,%3};"
                        : "+f"(acc[mt][nt][0]), "+f"(acc[mt][nt][1]),
                          "+f"(acc[mt][nt][2]), "+f"(acc[mt][nt][3])
                        : "r"(af[mt][0]), "r"(af[mt][1]),
                          "r"(af[mt][2]), "r"(af[mt][3]),
                          "r"(bf[nt][0]), "r"(bf[nt][1]));
                }
        }
        __syncthreads();
    }

    // epilogue: bias + relu, float2 stores
    #pragma unroll
    for (int mt = 0; mt < 2; mt++) {
        #pragma unroll
        for (int nt = 0; nt < 8; nt++) {
            int col = bn + wn + nt * 8 + 2 * tig;
            float b0 = bias[col], b1 = bias[col + 1];
            int r0 = bm + wm + mt * 16 + grp;
            if (r0 < M) {
                float2 c;
                c.x = fmaxf(acc[mt][nt][0] + b0, 0.f);
                c.y = fmaxf(acc[mt][nt][1] + b1, 0.f);
                *(float2*)(C + (size_t)r0 * N + col) = c;
            }
            if (r0 + 8 < M) {
                float2 c;
                c.x = fmaxf(acc[mt][nt][2] + b0, 0.f);
                c.y = fmaxf(acc[mt][nt][3] + b1, 0.f);
                *(float2*)(C + (size_t)(r0 + 8) * N + col) = c;
            }
        }
    }
}

// ---------------- pooling over sorted batch -----------------------------------
__global__ void graph_bounds(const void* __restrict__ batch,
                             const void* __restrict__ ei,
                             int* __restrict__ gstart) {
    int is64 = detect64(ei);
    int g = blockIdx.x * blockDim.x + threadIdx.x;
    if (g > N_GRAPHS) return;
    int lo = 0, hi = N_NODES;
    while (lo < hi) {
        int mid = (lo + hi) >> 1;
        if (idx_at(batch, mid, is64) < g) lo = mid + 1; else hi = mid;
    }
    gstart[g] = lo;
}

__global__ void pool_mean(const float* __restrict__ h,
                          const int* __restrict__ gstart,
                          float* __restrict__ pooled) {
    int g = blockIdx.x;
    int t = threadIdx.x;           // HID threads
    int beg = gstart[g], end = gstart[g + 1];
    float acc = 0.f;
    int n = beg;
    for (; n + 4 <= end; n += 4) {
        float a0 = h[(size_t)(n + 0) * HID + t];
        float a1 = h[(size_t)(n + 1) * HID + t];
        float a2 = h[(size_t)(n + 2) * HID + t];
        float a3 = h[(size_t)(n + 3) * HID + t];
        acc += a0 + a1 + a2 + a3;
    }
    for (; n < end; n++) acc += h[(size_t)n * HID + t];
    float c = fmaxf((float)(end - beg), 1.0f);
    pooled[(size_t)g * HID + t] = acc / c;
}

// ---------------- final MLP: out = relu(pooled@W1+b1)@W2+b2 ------------------
__global__ void final_mlp(const float* __restrict__ pooled,
                          const float* __restrict__ w1, const float* __restrict__ b1,
                          const float* __restrict__ w2, const float* __restrict__ b2,
                          float* __restrict__ out) {
    __shared__ float p[HID];
    __shared__ float hh[HID];
    int g = blockIdx.x;
    int t = threadIdx.x;

    p[t] = pooled[(size_t)g * HID + t];
    __syncthreads();

    float acc = b1[t];
    #pragma unroll 8
    for (int k = 0; k < HID; k++)
        acc += p[k] * w1[(size_t)k * HID + t];
    hh[t] = fmaxf(acc, 0.f);
    __syncthreads();

    int o  = t >> 4;
    int kk = t & 15;
    float s = 0.f;
    for (int k = kk; k < HID; k += 16)
        s += hh[k] * w2[(size_t)k * OUT_C + o];
    #pragma unroll
    for (int off = 8; off; off >>= 1)
        s += __shfl_xor_sync(0xffffffffu, s, off);
    if (kk == 0) out[(size_t)g * OUT_C + o] = s + b2[o];
}

// ---------------- launcher ----------------------------------------------------
extern "C" void kernel_launch(void* const* d_in, const int* in_sizes, int n_in,
                              void* d_out, int out_size)
{
    const float* x     = (const float*)d_in[0];
    const void*  ei    = d_in[1];
    const void*  batch = d_in[2];
    const float* w[16];
    for (int i = 0; i < 16; i++) w[i] = (const float*)d_in[3 + i];
    float* out = (float*)d_out;

    float *agg, *tmp, *h, *pool;
    int *deg, *rowptr, *cursor, *csr, *gstart;
    cudaGetSymbolAddress((void**)&agg,    g_agg);
    cudaGetSymbolAddress((void**)&tmp,    g_tmp);
    cudaGetSymbolAddress((void**)&h,      g_h);
    cudaGetSymbolAddress((void**)&pool,   g_pool);
    cudaGetSymbolAddress((void**)&deg,    g_deg);
    cudaGetSymbolAddress((void**)&rowptr, g_rowptr);
    cudaGetSymbolAddress((void**)&cursor, g_cursor);
    cudaGetSymbolAddress((void**)&csr,    g_csr);
    cudaGetSymbolAddress((void**)&gstart, g_gstart);

    // ---- CSR build (once, reused by all 3 layers) ----
    cudaMemsetAsync(deg, 0, N_NODES * sizeof(int));
    deg_hist<<<(N_EDGES + 255) / 256, 256>>>(ei, deg);              // launch 0
    scan_one<<<1, 1024>>>(deg, rowptr, cursor);                     // launch 1
    csr_fill<<<(N_EDGES + 255) / 256, 256>>>(ei, cursor, csr);      // launch 2

    // ---- 3 GIN layers ----
    for (int layer = 0; layer < 3; layer++) {
        const float* hin = (layer == 0) ? x : h;
        int K = (layer == 0) ? IN_C : HID;
        int c4shift = (layer == 0) ? 5 : 6;
        int npb = 256 >> c4shift;

        aggregate4<<<(N_NODES + npb - 1) / npb, 256>>>(             // launch 3 (L0)
            (const float4*)hin, rowptr, csr, (float4*)agg, c4shift);

        dim3 grid((N_NODES + GBM - 1) / GBM, HID / GBN);
        gemm_tf32<<<grid, 256>>>(agg, w[layer * 4 + 0], w[layer * 4 + 1],
                                 tmp, N_NODES, K, HID);
        gemm_tf32<<<grid, 256>>>(tmp, w[layer * 4 + 2], w[layer * 4 + 3],
                                 h, N_NODES, HID, HID);
    }

    // ---- pooling (batch is sorted) ----
    graph_bounds<<<3, 256>>>(batch, ei, gstart);
    pool_mean<<<N_GRAPHS, HID>>>(h, gstart, pool);

    final_mlp<<<N_GRAPHS, HID>>>(pool, w[12], w[13], w[14], w[15], out);
}

// round 12
// speedup vs baseline: 1.5814x; 1.0639x over previous
#include <cuda_runtime.h>
#include <cuda_bf16.h>
#include <cstdint>

#define N_NODES  50000
#define N_EDGES  800000
#define N_GRAPHS 512
#define IN_C     128
#define HID      256
#define OUT_C    16

// ---------------- scratch (static device globals; no allocation) -------------
__device__ float g_agg [(size_t)N_NODES * HID];
__device__ float g_tmp [(size_t)N_NODES * HID];
__device__ float g_h   [(size_t)N_NODES * HID];
__device__ float g_pool[N_GRAPHS * HID];
__device__ int   g_deg   [N_NODES];
__device__ int   g_ex    [N_NODES];
__device__ int   g_bsums [128];
__device__ int   g_rowptr[N_NODES + 1];
__device__ int   g_cursor[N_NODES];
__device__ int   g_csr   [N_EDGES];
__device__ int   g_gstart[N_GRAPHS + 1];

// ---------------- helpers -----------------------------------------------------
__device__ __forceinline__ int detect64(const void* ei) {
    const unsigned int* w = (const unsigned int*)ei;
    return ((w[1] | w[3] | w[5] | w[7]) == 0u) ? 1 : 0;
}
__device__ __forceinline__ int idx_at(const void* p, long long i, int is64) {
    if (is64) return (int)((const long long*)p)[i];
    return ((const int*)p)[i];
}
__device__ __forceinline__ uint32_t f2tf32(float f) {
    uint32_t r;
    asm("cvt.rna.tf32.f32 %0, %1;" : "=r"(r) : "f"(f));
    return r;
}

// ---------------- CSR build (R5 3-kernel scan — measured best) -----------------
__global__ void deg_hist(const void* __restrict__ ei, int* __restrict__ deg) {
    int is64 = detect64(ei);
    int e = blockIdx.x * blockDim.x + threadIdx.x;
    if (e >= N_EDGES) return;
    int d = idx_at(ei, (long long)N_EDGES + e, is64);
    atomicAdd(&deg[d], 1);
}

#define SCAN_B 512
__global__ void scan1(const int* __restrict__ deg, int* __restrict__ ex,
                      int* __restrict__ sums) {
    __shared__ int s[SCAN_B];
    int b = blockIdx.x, t = threadIdx.x;
    int i = b * SCAN_B + t;
    int v = (i < N_NODES) ? deg[i] : 0;
    s[t] = v; __syncthreads();
    for (int off = 1; off < SCAN_B; off <<= 1) {
        int x = (t >= off) ? s[t - off] : 0;
        __syncthreads();
        s[t] += x;
        __syncthreads();
    }
    if (i < N_NODES) ex[i] = s[t] - v;
    if (t == SCAN_B - 1) sums[b] = s[t];
}

__global__ void scan2(int* __restrict__ sums, int nb) {
    __shared__ int s[128];
    int t = threadIdx.x;
    int v = (t < nb) ? sums[t] : 0;
    s[t] = v; __syncthreads();
    for (int off = 1; off < 128; off <<= 1) {
        int x = (t >= off) ? s[t - off] : 0;
        __syncthreads();
        s[t] += x;
        __syncthreads();
    }
    if (t < nb) sums[t] = s[t] - v;
}

__global__ void scan3(const int* __restrict__ ex, const int* __restrict__ sums,
                      int* __restrict__ rowptr, int* __restrict__ cursor) {
    int i = blockIdx.x * blockDim.x + threadIdx.x;
    if (i < N_NODES) {
        int v = ex[i] + sums[i >> 9];
        rowptr[i] = v;
        cursor[i] = v;
    }
    if (i == 0) rowptr[N_NODES] = N_EDGES;
}

__global__ void csr_fill(const void* __restrict__ ei, int* __restrict__ cursor,
                         int* __restrict__ csr) {
    int is64 = detect64(ei);
    int e = blockIdx.x * blockDim.x + threadIdx.x;
    if (e >= N_EDGES) return;
    int s = idx_at(ei, e, is64);
    int d = idx_at(ei, (long long)N_EDGES + e, is64);
    int p = atomicAdd(&cursor[d], 1);
    csr[p] = s;
}

// ---------------- aggregation (exact R5 form - measured best) ------------------
__global__ void aggregate4(const float4* __restrict__ h4,
                           const int* __restrict__ rowptr,
                           const int* __restrict__ csr,
                           float4* __restrict__ out,
                           int c4shift)            // log2(C/4): 5 or 6
{
    int c4 = 1 << c4shift;
    int sub  = threadIdx.x >> c4shift;
    int t    = threadIdx.x & (c4 - 1);
    int npb  = 256 >> c4shift;
    int node = blockIdx.x * npb + sub;
    if (node >= N_NODES) return;

    int beg = rowptr[node], end = rowptr[node + 1];
    float4 acc = h4[((size_t)node << c4shift) + t];
    int e = beg;
    for (; e + 4 <= end; e += 4) {
        int s0 = csr[e], s1 = csr[e + 1], s2 = csr[e + 2], s3 = csr[e + 3];
        float4 v0 = h4[((size_t)s0 << c4shift) + t];
        float4 v1 = h4[((size_t)s1 << c4shift) + t];
        float4 v2 = h4[((size_t)s2 << c4shift) + t];
        float4 v3 = h4[((size_t)s3 << c4shift) + t];
        acc.x += v0.x + v1.x + v2.x + v3.x;
        acc.y += v0.y + v1.y + v2.y + v3.y;
        acc.z += v0.z + v1.z + v2.z + v3.z;
        acc.w += v0.w + v1.w + v2.w + v3.w;
    }
    for (; e < end; e++) {
        float4 v = h4[((size_t)csr[e] << c4shift) + t];
        acc.x += v.x; acc.y += v.y; acc.z += v.z; acc.w += v.w;
    }
    out[((size_t)node << c4shift) + t] = acc;
}

// ---------------- TF32 tensor-core GEMM: BN=64, occupancy 3 -------------------
// Same layout residues as R5 (ASTRIDE 36; BSTRIDE 72 == 136 mod 32).
// 8 warps as 4m x 2n, warp tile 32x32, acc[2][4][4] -> ~half the registers.
#define GBM 128
#define GBN 64
#define GBK 32
#define ASTRIDE 36
#define BSTRIDE 72

__global__ __launch_bounds__(256, 3)
void gemm_tf32(const float* __restrict__ A,
               const float* __restrict__ W,      // K x N row-major
               const float* __restrict__ bias,   // N
               float* __restrict__ C,
               int M, int K, int N)
{
    __shared__ uint32_t As[GBM][ASTRIDE];
    __shared__ uint32_t Bs[GBK][BSTRIDE];

    int bm = blockIdx.x * GBM;
    int bn = blockIdx.y * GBN;
    int tid  = threadIdx.x;
    int wid  = tid >> 5;
    int lane = tid & 31;
    int grp  = lane >> 2;     // 0..7
    int tig  = lane & 3;      // 0..3
    int wm = (wid & 3) * 32;  // warp row offset in tile
    int wn = (wid >> 2) * 32; // warp col offset in tile

    float acc[2][4][4];
    #pragma unroll
    for (int i = 0; i < 2; i++)
        #pragma unroll
        for (int j = 0; j < 4; j++)
            #pragma unroll
            for (int r = 0; r < 4; r++) acc[i][j][r] = 0.f;

    float4 pa[4], pb[2];

    auto ld_tiles = [&](int k0) {
        #pragma unroll
        for (int i = 0; i < 4; i++) {
            int li = tid + i * 256;
            int r  = li >> 3;          // 0..127
            int cq = (li & 7) * 4;     // 0..28
            int row = bm + r;
            pa[i] = (row < M) ? *(const float4*)(A + (size_t)row * K + k0 + cq)
                              : make_float4(0.f, 0.f, 0.f, 0.f);
        }
        #pragma unroll
        for (int i = 0; i < 2; i++) {
            int li = tid + i * 256;
            int kr = li >> 4;          // 0..31
            int cq = (li & 15) * 4;    // 0..60
            pb[i] = *(const float4*)(W + (size_t)(k0 + kr) * N + bn + cq);
        }
    };

    auto st_tiles = [&]() {
        #pragma unroll
        for (int i = 0; i < 4; i++) {
            int li = tid + i * 256;
            int r  = li >> 3;
            int cq = (li & 7) * 4;
            As[r][cq + 0] = f2tf32(pa[i].x);
            As[r][cq + 1] = f2tf32(pa[i].y);
            As[r][cq + 2] = f2tf32(pa[i].z);
            As[r][cq + 3] = f2tf32(pa[i].w);
        }
        #pragma unroll
        for (int i = 0; i < 2; i++) {
            int li = tid + i * 256;
            int kr = li >> 4;
            int cq = (li & 15) * 4;
            Bs[kr][cq + 0] = f2tf32(pb[i].x);
            Bs[kr][cq + 1] = f2tf32(pb[i].y);
            Bs[kr][cq + 2] = f2tf32(pb[i].z);
            Bs[kr][cq + 3] = f2tf32(pb[i].w);
        }
    };

    ld_tiles(0);

    for (int k0 = 0; k0 < K; k0 += GBK) {
        st_tiles();
        __syncthreads();
        if (k0 + GBK < K) ld_tiles(k0 + GBK);   // hide LDG behind MMA phase

        #pragma unroll
        for (int ks = 0; ks < GBK; ks += 8) {
            uint32_t af[2][4];
            #pragma unroll
            for (int mt = 0; mt < 2; mt++) {
                int r0 = wm + mt * 16 + grp;
                af[mt][0] = As[r0][ks + tig];
                af[mt][1] = As[r0 + 8][ks + tig];
                af[mt][2] = As[r0][ks + tig + 4];
                af[mt][3] = As[r0 + 8][ks + tig + 4];
            }
            uint32_t bf[4][2];
            #pragma unroll
            for (int nt = 0; nt < 4; nt++) {
                int c0 = wn + nt * 8 + grp;
                bf[nt][0] = Bs[ks + tig][c0];
                bf[nt][1] = Bs[ks + tig + 4][c0];
            }
            #pragma unroll
            for (int mt = 0; mt < 2; mt++)
                #pragma unroll
                for (int nt = 0; nt < 4; nt++) {
                    asm volatile(
                        "mma.sync.aligned.m16n8k8.row.col.f32.tf32.tf32.f32 "
                        "{%0,%1,%2,%3}, {%4,%5,%6,%7}, {%8,%9}, {%0,%1,%2,%3};"
                        : "+f"(acc[mt][nt][0]), "+f"(acc[mt][nt][1]),
                          "+f"(acc[mt][nt][2]), "+f"(acc[mt][nt][3])
                        : "r"(af[mt][0]), "r"(af[mt][1]),
                          "r"(af[mt][2]), "r"(af[mt][3]),
                          "r"(bf[nt][0]), "r"(bf[nt][1]));
                }
        }
        __syncthreads();
    }

    // epilogue: bias + relu, float2 stores
    #pragma unroll
    for (int mt = 0; mt < 2; mt++) {
        #pragma unroll
        for (int nt = 0; nt < 4; nt++) {
            int col = bn + wn + nt * 8 + 2 * tig;
            float b0 = bias[col], b1 = bias[col + 1];
            int r0 = bm + wm + mt * 16 + grp;
            if (r0 < M) {
                float2 c;
                c.x = fmaxf(acc[mt][nt][0] + b0, 0.f);
                c.y = fmaxf(acc[mt][nt][1] + b1, 0.f);
                *(float2*)(C + (size_t)r0 * N + col) = c;
            }
            if (r0 + 8 < M) {
                float2 c;
                c.x = fmaxf(acc[mt][nt][2] + b0, 0.f);
                c.y = fmaxf(acc[mt][nt][3] + b1, 0.f);
                *(float2*)(C + (size_t)(r0 + 8) * N + col) = c;
            }
        }
    }
}

// ---------------- pooling over sorted batch -----------------------------------
__global__ void graph_bounds(const void* __restrict__ batch,
                             const void* __restrict__ ei,
                             int* __restrict__ gstart) {
    int is64 = detect64(ei);
    int g = blockIdx.x * blockDim.x + threadIdx.x;
    if (g > N_GRAPHS) return;
    int lo = 0, hi = N_NODES;
    while (lo < hi) {
        int mid = (lo + hi) >> 1;
        if (idx_at(batch, mid, is64) < g) lo = mid + 1; else hi = mid;
    }
    gstart[g] = lo;
}

__global__ void pool_mean(const float* __restrict__ h,
                          const int* __restrict__ gstart,
                          float* __restrict__ pooled) {
    int g = blockIdx.x;
    int t = threadIdx.x;           // HID threads
    int beg = gstart[g], end = gstart[g + 1];
    float acc = 0.f;
    int n = beg;
    for (; n + 4 <= end; n += 4) {
        float a0 = h[(size_t)(n + 0) * HID + t];
        float a1 = h[(size_t)(n + 1) * HID + t];
        float a2 = h[(size_t)(n + 2) * HID + t];
        float a3 = h[(size_t)(n + 3) * HID + t];
        acc += a0 + a1 + a2 + a3;
    }
    for (; n < end; n++) acc += h[(size_t)n * HID + t];
    float c = fmaxf((float)(end - beg), 1.0f);
    pooled[(size_t)g * HID + t] = acc / c;
}

// ---------------- final MLP: out = relu(pooled@W1+b1)@W2+b2 ------------------
__global__ void final_mlp(const float* __restrict__ pooled,
                          const float* __restrict__ w1, const float* __restrict__ b1,
                          const float* __restrict__ w2, const float* __restrict__ b2,
                          float* __restrict__ out) {
    __shared__ float p[HID];
    __shared__ float hh[HID];
    int g = blockIdx.x;
    int t = threadIdx.x;

    p[t] = pooled[(size_t)g * HID + t];
    __syncthreads();

    float acc = b1[t];
    #pragma unroll 8
    for (int k = 0; k < HID; k++)
        acc += p[k] * w1[(size_t)k * HID + t];
    hh[t] = fmaxf(acc, 0.f);
    __syncthreads();

    int o  = t >> 4;
    int kk = t & 15;
    float s = 0.f;
    for (int k = kk; k < HID; k += 16)
        s += hh[k] * w2[(size_t)k * OUT_C + o];
    #pragma unroll
    for (int off = 8; off; off >>= 1)
        s += __shfl_xor_sync(0xffffffffu, s, off);
    if (kk == 0) out[(size_t)g * OUT_C + o] = s + b2[o];
}

// ---------------- launcher ----------------------------------------------------
extern "C" void kernel_launch(void* const* d_in, const int* in_sizes, int n_in,
                              void* d_out, int out_size)
{
    const float* x     = (const float*)d_in[0];
    const void*  ei    = d_in[1];
    const void*  batch = d_in[2];
    const float* w[16];
    for (int i = 0; i < 16; i++) w[i] = (const float*)d_in[3 + i];
    float* out = (float*)d_out;

    float *agg, *tmp, *h, *pool;
    int *deg, *ex, *bsums, *rowptr, *cursor, *csr, *gstart;
    cudaGetSymbolAddress((void**)&agg,    g_agg);
    cudaGetSymbolAddress((void**)&tmp,    g_tmp);
    cudaGetSymbolAddress((void**)&h,      g_h);
    cudaGetSymbolAddress((void**)&pool,   g_pool);
    cudaGetSymbolAddress((void**)&deg,    g_deg);
    cudaGetSymbolAddress((void**)&ex,     g_ex);
    cudaGetSymbolAddress((void**)&bsums,  g_bsums);
    cudaGetSymbolAddress((void**)&rowptr, g_rowptr);
    cudaGetSymbolAddress((void**)&cursor, g_cursor);
    cudaGetSymbolAddress((void**)&csr,    g_csr);
    cudaGetSymbolAddress((void**)&gstart, g_gstart);

    // ---- CSR build (once, reused by all 3 layers) ----
    cudaMemsetAsync(deg, 0, N_NODES * sizeof(int));
    deg_hist<<<(N_EDGES + 255) / 256, 256>>>(ei, deg);
    int nb = (N_NODES + SCAN_B - 1) / SCAN_B;   // 98
    scan1<<<nb, SCAN_B>>>(deg, ex, bsums);
    scan2<<<1, 128>>>(bsums, nb);
    scan3<<<(N_NODES + 256) / 256, 256>>>(ex, bsums, rowptr, cursor);
    csr_fill<<<(N_EDGES + 255) / 256, 256>>>(ei, cursor, csr);

    // ---- 3 GIN layers ----
    for (int layer = 0; layer < 3; layer++) {
        const float* hin = (layer == 0) ? x : h;
        int K = (layer == 0) ? IN_C : HID;
        int c4shift = (layer == 0) ? 5 : 6;
        int npb = 256 >> c4shift;

        aggregate4<<<(N_NODES + npb - 1) / npb, 256>>>(
            (const float4*)hin, rowptr, csr, (float4*)agg, c4shift);

        dim3 grid((N_NODES + GBM - 1) / GBM, HID / GBN);
        gemm_tf32<<<grid, 256>>>(agg, w[layer * 4 + 0], w[layer * 4 + 1],
                                 tmp, N_NODES, K, HID);
        gemm_tf32<<<grid, 256>>>(tmp, w[layer * 4 + 2], w[layer * 4 + 3],
                                 h, N_NODES, HID, HID);
    }

    // ---- pooling (batch is sorted) ----
    graph_bounds<<<3, 256>>>(batch, ei, gstart);
    pool_mean<<<N_GRAPHS, HID>>>(h, gstart, pool);

    final_mlp<<<N_GRAPHS, HID>>>(pool, w[12], w[13], w[14], w[15], out);
}

// round 13
// speedup vs baseline: 1.6333x; 1.0328x over previous
#include <cuda_runtime.h>
#include <cuda_bf16.h>
#include <cstdint>

#define N_NODES  50000
#define N_EDGES  800000
#define N_GRAPHS 512
#define IN_C     128
#define HID      256
#define OUT_C    16

// ---------------- scratch (static device globals; no allocation) -------------
__device__ float g_agg [(size_t)N_NODES * HID];
__device__ float g_tmp [(size_t)N_NODES * HID];
__device__ float g_h   [(size_t)N_NODES * HID];
__device__ float g_pool[N_GRAPHS * HID];
__device__ int   g_deg   [N_NODES];
__device__ int   g_ex    [N_NODES];
__device__ int   g_bsums [128];
__device__ int   g_rowptr[N_NODES + 1];
__device__ int   g_cursor[N_NODES];
__device__ int   g_csr   [N_EDGES];
__device__ int   g_gstart[N_GRAPHS + 1];

// ---------------- helpers -----------------------------------------------------
__device__ __forceinline__ int detect64(const void* ei) {
    const unsigned int* w = (const unsigned int*)ei;
    return ((w[1] | w[3] | w[5] | w[7]) == 0u) ? 1 : 0;
}
__device__ __forceinline__ int idx_at(const void* p, long long i, int is64) {
    if (is64) return (int)((const long long*)p)[i];
    return ((const int*)p)[i];
}
__device__ __forceinline__ uint32_t f2tf32(float f) {
    uint32_t r;
    asm("cvt.rna.tf32.f32 %0, %1;" : "=r"(r) : "f"(f));
    return r;
}

// ---------------- CSR build (R5 3-kernel scan — measured best) -----------------
__global__ void deg_hist(const void* __restrict__ ei, int* __restrict__ deg) {
    int is64 = detect64(ei);
    int e = blockIdx.x * blockDim.x + threadIdx.x;
    if (e >= N_EDGES) return;
    int d = idx_at(ei, (long long)N_EDGES + e, is64);
    atomicAdd(&deg[d], 1);
}

#define SCAN_B 512
__global__ void scan1(const int* __restrict__ deg, int* __restrict__ ex,
                      int* __restrict__ sums) {
    __shared__ int s[SCAN_B];
    int b = blockIdx.x, t = threadIdx.x;
    int i = b * SCAN_B + t;
    int v = (i < N_NODES) ? deg[i] : 0;
    s[t] = v; __syncthreads();
    for (int off = 1; off < SCAN_B; off <<= 1) {
        int x = (t >= off) ? s[t - off] : 0;
        __syncthreads();
        s[t] += x;
        __syncthreads();
    }
    if (i < N_NODES) ex[i] = s[t] - v;
    if (t == SCAN_B - 1) sums[b] = s[t];
}

__global__ void scan2(int* __restrict__ sums, int nb) {
    __shared__ int s[128];
    int t = threadIdx.x;
    int v = (t < nb) ? sums[t] : 0;
    s[t] = v; __syncthreads();
    for (int off = 1; off < 128; off <<= 1) {
        int x = (t >= off) ? s[t - off] : 0;
        __syncthreads();
        s[t] += x;
        __syncthreads();
    }
    if (t < nb) sums[t] = s[t] - v;
}

__global__ void scan3(const int* __restrict__ ex, const int* __restrict__ sums,
                      int* __restrict__ rowptr, int* __restrict__ cursor) {
    int i = blockIdx.x * blockDim.x + threadIdx.x;
    if (i < N_NODES) {
        int v = ex[i] + sums[i >> 9];
        rowptr[i] = v;
        cursor[i] = v;
    }
    if (i == 0) rowptr[N_NODES] = N_EDGES;
}

__global__ void csr_fill(const void* __restrict__ ei, int* __restrict__ cursor,
                         int* __restrict__ csr) {
    int is64 = detect64(ei);
    int e = blockIdx.x * blockDim.x + threadIdx.x;
    if (e >= N_EDGES) return;
    int s = idx_at(ei, e, is64);
    int d = idx_at(ei, (long long)N_EDGES + e, is64);
    int p = atomicAdd(&cursor[d], 1);
    csr[p] = s;
}

// ---------------- aggregation (exact R5 form - measured best) ------------------
__global__ void aggregate4(const float4* __restrict__ h4,
                           const int* __restrict__ rowptr,
                           const int* __restrict__ csr,
                           float4* __restrict__ out,
                           int c4shift)            // log2(C/4): 5 or 6
{
    int c4 = 1 << c4shift;
    int sub  = threadIdx.x >> c4shift;
    int t    = threadIdx.x & (c4 - 1);
    int npb  = 256 >> c4shift;
    int node = blockIdx.x * npb + sub;
    if (node >= N_NODES) return;

    int beg = rowptr[node], end = rowptr[node + 1];
    float4 acc = h4[((size_t)node << c4shift) + t];
    int e = beg;
    for (; e + 4 <= end; e += 4) {
        int s0 = csr[e], s1 = csr[e + 1], s2 = csr[e + 2], s3 = csr[e + 3];
        float4 v0 = h4[((size_t)s0 << c4shift) + t];
        float4 v1 = h4[((size_t)s1 << c4shift) + t];
        float4 v2 = h4[((size_t)s2 << c4shift) + t];
        float4 v3 = h4[((size_t)s3 << c4shift) + t];
        acc.x += v0.x + v1.x + v2.x + v3.x;
        acc.y += v0.y + v1.y + v2.y + v3.y;
        acc.z += v0.z + v1.z + v2.z + v3.z;
        acc.w += v0.w + v1.w + v2.w + v3.w;
    }
    for (; e < end; e++) {
        float4 v = h4[((size_t)csr[e] << c4shift) + t];
        acc.x += v.x; acc.y += v.y; acc.z += v.z; acc.w += v.w;
    }
    out[((size_t)node << c4shift) + t] = acc;
}

// ---------------- TF32 tensor-core GEMM (R5 layout + smem double-buffer) ------
// Identical index math / strides to R5; only a buffer-select offset alternates.
// One __syncthreads per k-iter instead of two.
#define GBM 128
#define GBN 128
#define GBK 32
#define ASTRIDE 36
#define BSTRIDE 136
#define AWORDS (GBM * ASTRIDE)          // 4608
#define BWORDS (GBK * BSTRIDE)          // 4352
#define BUFWORDS (AWORDS + BWORDS)      // 8960 words = 35840 B
#define GEMM_SMEM (2 * BUFWORDS * 4)    // 71680 B dynamic

__global__ __launch_bounds__(256, 2)
void gemm_tf32(const float* __restrict__ A,
               const float* __restrict__ W,      // K x N row-major
               const float* __restrict__ bias,   // N
               float* __restrict__ C,
               int M, int K, int N)
{
    extern __shared__ __align__(16) uint32_t Sm[];

    int bm = blockIdx.x * GBM;
    int bn = blockIdx.y * GBN;
    int tid  = threadIdx.x;
    int wid  = tid >> 5;
    int lane = tid & 31;
    int grp  = lane >> 2;     // 0..7
    int tig  = lane & 3;      // 0..3
    int wm = (wid & 3) * 32;  // warp row offset in tile
    int wn = (wid >> 2) * 64; // warp col offset in tile

    float acc[2][8][4];
    #pragma unroll
    for (int i = 0; i < 2; i++)
        #pragma unroll
        for (int j = 0; j < 8; j++)
            #pragma unroll
            for (int r = 0; r < 4; r++) acc[i][j][r] = 0.f;

    float4 pa[4], pb[4];

    auto ld_tiles = [&](int k0) {
        #pragma unroll
        for (int i = 0; i < 4; i++) {
            int li = tid + i * 256;
            int r  = li >> 3;          // 0..127
            int cq = (li & 7) * 4;     // 0..28
            int row = bm + r;
            pa[i] = (row < M) ? *(const float4*)(A + (size_t)row * K + k0 + cq)
                              : make_float4(0.f, 0.f, 0.f, 0.f);
        }
        #pragma unroll
        for (int i = 0; i < 4; i++) {
            int li = tid + i * 256;
            int kr = li >> 5;          // 0..31
            int cq = (li & 31) * 4;    // 0..124
            pb[i] = *(const float4*)(W + (size_t)(k0 + kr) * N + bn + cq);
        }
    };

    auto st_tiles = [&](int buf) {
        uint32_t* As = Sm + buf * BUFWORDS;
        uint32_t* Bs = As + AWORDS;
        #pragma unroll
        for (int i = 0; i < 4; i++) {
            int li = tid + i * 256;
            int r  = li >> 3;
            int cq = (li & 7) * 4;
            uint32_t* p = As + r * ASTRIDE + cq;
            p[0] = f2tf32(pa[i].x);
            p[1] = f2tf32(pa[i].y);
            p[2] = f2tf32(pa[i].z);
            p[3] = f2tf32(pa[i].w);
        }
        #pragma unroll
        for (int i = 0; i < 4; i++) {
            int li = tid + i * 256;
            int kr = li >> 5;
            int cq = (li & 31) * 4;
            uint32_t* p = Bs + kr * BSTRIDE + cq;
            p[0] = f2tf32(pb[i].x);
            p[1] = f2tf32(pb[i].y);
            p[2] = f2tf32(pb[i].z);
            p[3] = f2tf32(pb[i].w);
        }
    };

    ld_tiles(0);
    int niter = K / GBK;

    for (int it = 0; it < niter; it++) {
        st_tiles(it & 1);
        if (it + 1 < niter) ld_tiles((it + 1) * GBK);   // overlap LDG with MMA
        __syncthreads();

        const uint32_t* As = Sm + (it & 1) * BUFWORDS;
        const uint32_t* Bs = As + AWORDS;

        #pragma unroll
        for (int ks = 0; ks < GBK; ks += 8) {
            uint32_t af[2][4];
            #pragma unroll
            for (int mt = 0; mt < 2; mt++) {
                int r0 = wm + mt * 16 + grp;
                af[mt][0] = As[r0 * ASTRIDE + ks + tig];
                af[mt][1] = As[(r0 + 8) * ASTRIDE + ks + tig];
                af[mt][2] = As[r0 * ASTRIDE + ks + tig + 4];
                af[mt][3] = As[(r0 + 8) * ASTRIDE + ks + tig + 4];
            }
            uint32_t bf[8][2];
            #pragma unroll
            for (int nt = 0; nt < 8; nt++) {
                int c0 = wn + nt * 8 + grp;
                bf[nt][0] = Bs[(ks + tig) * BSTRIDE + c0];
                bf[nt][1] = Bs[(ks + tig + 4) * BSTRIDE + c0];
            }
            #pragma unroll
            for (int mt = 0; mt < 2; mt++)
                #pragma unroll
                for (int nt = 0; nt < 8; nt++) {
                    asm volatile(
                        "mma.sync.aligned.m16n8k8.row.col.f32.tf32.tf32.f32 "
                        "{%0,%1,%2,%3}, {%4,%5,%6,%7}, {%8,%9}, {%0,%1,%2,%3};"
                        : "+f"(acc[mt][nt][0]), "+f"(acc[mt][nt][1]),
                          "+f"(acc[mt][nt][2]), "+f"(acc[mt][nt][3])
                        : "r"(af[mt][0]), "r"(af[mt][1]),
                          "r"(af[mt][2]), "r"(af[mt][3]),
                          "r"(bf[nt][0]), "r"(bf[nt][1]));
                }
        }
        // no second barrier: next iter's st_tiles writes the OTHER buffer;
        // the following iteration's single barrier fences reuse of this one.
    }

    // epilogue: bias + relu, float2 stores
    #pragma unroll
    for (int mt = 0; mt < 2; mt++) {
        #pragma unroll
        for (int nt = 0; nt < 8; nt++) {
            int col = bn + wn + nt * 8 + 2 * tig;
            float b0 = bias[col], b1 = bias[col + 1];
            int r0 = bm + wm + mt * 16 + grp;
            if (r0 < M) {
                float2 c;
                c.x = fmaxf(acc[mt][nt][0] + b0, 0.f);
                c.y = fmaxf(acc[mt][nt][1] + b1, 0.f);
                *(float2*)(C + (size_t)r0 * N + col) = c;
            }
            if (r0 + 8 < M) {
                float2 c;
                c.x = fmaxf(acc[mt][nt][2] + b0, 0.f);
                c.y = fmaxf(acc[mt][nt][3] + b1, 0.f);
                *(float2*)(C + (size_t)(r0 + 8) * N + col) = c;
            }
        }
    }
}

// ---------------- pooling over sorted batch -----------------------------------
__global__ void graph_bounds(const void* __restrict__ batch,
                             const void* __restrict__ ei,
                             int* __restrict__ gstart) {
    int is64 = detect64(ei);
    int g = blockIdx.x * blockDim.x + threadIdx.x;
    if (g > N_GRAPHS) return;
    int lo = 0, hi = N_NODES;
    while (lo < hi) {
        int mid = (lo + hi) >> 1;
        if (idx_at(batch, mid, is64) < g) lo = mid + 1; else hi = mid;
    }
    gstart[g] = lo;
}

__global__ void pool_mean(const float* __restrict__ h,
                          const int* __restrict__ gstart,
                          float* __restrict__ pooled) {
    int g = blockIdx.x;
    int t = threadIdx.x;           // HID threads
    int beg = gstart[g], end = gstart[g + 1];
    float acc = 0.f;
    int n = beg;
    for (; n + 4 <= end; n += 4) {
        float a0 = h[(size_t)(n + 0) * HID + t];
        float a1 = h[(size_t)(n + 1) * HID + t];
        float a2 = h[(size_t)(n + 2) * HID + t];
        float a3 = h[(size_t)(n + 3) * HID + t];
        acc += a0 + a1 + a2 + a3;
    }
    for (; n < end; n++) acc += h[(size_t)n * HID + t];
    float c = fmaxf((float)(end - beg), 1.0f);
    pooled[(size_t)g * HID + t] = acc / c;
}

// ---------------- final MLP: out = relu(pooled@W1+b1)@W2+b2 ------------------
__global__ void final_mlp(const float* __restrict__ pooled,
                          const float* __restrict__ w1, const float* __restrict__ b1,
                          const float* __restrict__ w2, const float* __restrict__ b2,
                          float* __restrict__ out) {
    __shared__ float p[HID];
    __shared__ float hh[HID];
    int g = blockIdx.x;
    int t = threadIdx.x;

    p[t] = pooled[(size_t)g * HID + t];
    __syncthreads();

    float acc = b1[t];
    #pragma unroll 8
    for (int k = 0; k < HID; k++)
        acc += p[k] * w1[(size_t)k * HID + t];
    hh[t] = fmaxf(acc, 0.f);
    __syncthreads();

    int o  = t >> 4;
    int kk = t & 15;
    float s = 0.f;
    for (int k = kk; k < HID; k += 16)
        s += hh[k] * w2[(size_t)k * OUT_C + o];
    #pragma unroll
    for (int off = 8; off; off >>= 1)
        s += __shfl_xor_sync(0xffffffffu, s, off);
    if (kk == 0) out[(size_t)g * OUT_C + o] = s + b2[o];
}

// ---------------- launcher ----------------------------------------------------
extern "C" void kernel_launch(void* const* d_in, const int* in_sizes, int n_in,
                              void* d_out, int out_size)
{
    const float* x     = (const float*)d_in[0];
    const void*  ei    = d_in[1];
    const void*  batch = d_in[2];
    const float* w[16];
    for (int i = 0; i < 16; i++) w[i] = (const float*)d_in[3 + i];
    float* out = (float*)d_out;

    float *agg, *tmp, *h, *pool;
    int *deg, *ex, *bsums, *rowptr, *cursor, *csr, *gstart;
    cudaGetSymbolAddress((void**)&agg,    g_agg);
    cudaGetSymbolAddress((void**)&tmp,    g_tmp);
    cudaGetSymbolAddress((void**)&h,      g_h);
    cudaGetSymbolAddress((void**)&pool,   g_pool);
    cudaGetSymbolAddress((void**)&deg,    g_deg);
    cudaGetSymbolAddress((void**)&ex,     g_ex);
    cudaGetSymbolAddress((void**)&bsums,  g_bsums);
    cudaGetSymbolAddress((void**)&rowptr, g_rowptr);
    cudaGetSymbolAddress((void**)&cursor, g_cursor);
    cudaGetSymbolAddress((void**)&csr,    g_csr);
    cudaGetSymbolAddress((void**)&gstart, g_gstart);

    cudaFuncSetAttribute(gemm_tf32,
                         cudaFuncAttributeMaxDynamicSharedMemorySize, GEMM_SMEM);

    // ---- CSR build (once, reused by all 3 layers) ----
    cudaMemsetAsync(deg, 0, N_NODES * sizeof(int));
    deg_hist<<<(N_EDGES + 255) / 256, 256>>>(ei, deg);
    int nb = (N_NODES + SCAN_B - 1) / SCAN_B;   // 98
    scan1<<<nb, SCAN_B>>>(deg, ex, bsums);
    scan2<<<1, 128>>>(bsums, nb);
    scan3<<<(N_NODES + 256) / 256, 256>>>(ex, bsums, rowptr, cursor);
    csr_fill<<<(N_EDGES + 255) / 256, 256>>>(ei, cursor, csr);

    // ---- 3 GIN layers ----
    for (int layer = 0; layer < 3; layer++) {
        const float* hin = (layer == 0) ? x : h;
        int K = (layer == 0) ? IN_C : HID;
        int c4shift = (layer == 0) ? 5 : 6;
        int npb = 256 >> c4shift;

        aggregate4<<<(N_NODES + npb - 1) / npb, 256>>>(
            (const float4*)hin, rowptr, csr, (float4*)agg, c4shift);

        dim3 grid((N_NODES + GBM - 1) / GBM, HID / GBN);
        gemm_tf32<<<grid, 256, GEMM_SMEM>>>(agg, w[layer * 4 + 0],
                                            w[layer * 4 + 1], tmp,
                                            N_NODES, K, HID);
        gemm_tf32<<<grid, 256, GEMM_SMEM>>>(tmp, w[layer * 4 + 2],
                                            w[layer * 4 + 3], h,
                                            N_NODES, HID, HID);
    }

    // ---- pooling (batch is sorted) ----
    graph_bounds<<<3, 256>>>(batch, ei, gstart);
    pool_mean<<<N_GRAPHS, HID>>>(h, gstart, pool);

    final_mlp<<<N_GRAPHS, HID>>>(pool, w[12], w[13], w[14], w[15], out);
}

// round 16
// speedup vs baseline: 2.0854x; 1.2768x over previous
#include <cuda_runtime.h>
#include <cuda_bf16.h>
#include <cuda_fp16.h>
#include <cstdint>

#define N_NODES  50000
#define N_EDGES  800000
#define N_GRAPHS 512
#define IN_C     128
#define HID      256
#define OUT_C    16

// ---------------- scratch (static device globals; no allocation) -------------
__device__ float g_agg [(size_t)N_NODES * HID];
__device__ float g_tmp [(size_t)N_NODES * HID];
__device__ float g_h   [(size_t)N_NODES * HID];
__device__ float g_pool[N_GRAPHS * HID];
__device__ int   g_deg   [N_NODES];
__device__ int   g_ex    [N_NODES];
__device__ int   g_bsums [128];
__device__ int   g_rowptr[N_NODES + 1];
__device__ int   g_cursor[N_NODES];
__device__ int   g_csr   [N_EDGES];
__device__ int   g_gstart[N_GRAPHS + 1];

// ---------------- helpers -----------------------------------------------------
__device__ __forceinline__ int detect64(const void* ei) {
    const unsigned int* w = (const unsigned int*)ei;
    return ((w[1] | w[3] | w[5] | w[7]) == 0u) ? 1 : 0;
}
__device__ __forceinline__ int idx_at(const void* p, long long i, int is64) {
    if (is64) return (int)((const long long*)p)[i];
    return ((const int*)p)[i];
}
// pack two floats into f16x2 (lo = first arg)
__device__ __forceinline__ uint32_t f2h2(float lo, float hi) {
    __half2 h = __floats2half2_rn(lo, hi);
    return *(uint32_t*)&h;
}

// ---------------- CSR build (R5 form — measured best) --------------------------
__global__ void deg_hist(const void* __restrict__ ei, int* __restrict__ deg) {
    int is64 = detect64(ei);
    int e = blockIdx.x * blockDim.x + threadIdx.x;
    if (e >= N_EDGES) return;
    int d = idx_at(ei, (long long)N_EDGES + e, is64);
    atomicAdd(&deg[d], 1);
}

#define SCAN_B 512
__global__ void scan1(const int* __restrict__ deg, int* __restrict__ ex,
                      int* __restrict__ sums) {
    __shared__ int s[SCAN_B];
    int b = blockIdx.x, t = threadIdx.x;
    int i = b * SCAN_B + t;
    int v = (i < N_NODES) ? deg[i] : 0;
    s[t] = v; __syncthreads();
    for (int off = 1; off < SCAN_B; off <<= 1) {
        int x = (t >= off) ? s[t - off] : 0;
        __syncthreads();
        s[t] += x;
        __syncthreads();
    }
    if (i < N_NODES) ex[i] = s[t] - v;
    if (t == SCAN_B - 1) sums[b] = s[t];
}

__global__ void scan2(int* __restrict__ sums, int nb) {
    __shared__ int s[128];
    int t = threadIdx.x;
    int v = (t < nb) ? sums[t] : 0;
    s[t] = v; __syncthreads();
    for (int off = 1; off < 128; off <<= 1) {
        int x = (t >= off) ? s[t - off] : 0;
        __syncthreads();
        s[t] += x;
        __syncthreads();
    }
    if (t < nb) sums[t] = s[t] - v;
}

__global__ void scan3(const int* __restrict__ ex, const int* __restrict__ sums,
                      int* __restrict__ rowptr, int* __restrict__ cursor) {
    int i = blockIdx.x * blockDim.x + threadIdx.x;
    if (i < N_NODES) {
        int v = ex[i] + sums[i >> 9];
        rowptr[i] = v;
        cursor[i] = v;
    }
    if (i == 0) rowptr[N_NODES] = N_EDGES;
}

__global__ void csr_fill(const void* __restrict__ ei, int* __restrict__ cursor,
                         int* __restrict__ csr) {
    int is64 = detect64(ei);
    int e = blockIdx.x * blockDim.x + threadIdx.x;
    if (e >= N_EDGES) return;
    int s = idx_at(ei, e, is64);
    int d = idx_at(ei, (long long)N_EDGES + e, is64);
    int p = atomicAdd(&cursor[d], 1);
    csr[p] = s;
}

// ---------------- aggregation (exact R5 form — measured best) ------------------
__global__ void aggregate4(const float4* __restrict__ h4,
                           const int* __restrict__ rowptr,
                           const int* __restrict__ csr,
                           float4* __restrict__ out,
                           int c4shift) {
    int c4 = 1 << c4shift;
    int sub  = threadIdx.x >> c4shift;
    int t    = threadIdx.x & (c4 - 1);
    int npb  = 256 >> c4shift;
    int node = blockIdx.x * npb + sub;
    if (node >= N_NODES) return;

    int beg = rowptr[node], end = rowptr[node + 1];
    float4 acc = h4[((size_t)node << c4shift) + t];
    int e = beg;
    for (; e + 4 <= end; e += 4) {
        int s0 = csr[e], s1 = csr[e + 1], s2 = csr[e + 2], s3 = csr[e + 3];
        float4 v0 = h4[((size_t)s0 << c4shift) + t];
        float4 v1 = h4[((size_t)s1 << c4shift) + t];
        float4 v2 = h4[((size_t)s2 << c4shift) + t];
        float4 v3 = h4[((size_t)s3 << c4shift) + t];
        acc.x += v0.x + v1.x + v2.x + v3.x;
        acc.y += v0.y + v1.y + v2.y + v3.y;
        acc.z += v0.z + v1.z + v2.z + v3.z;
        acc.w += v0.w + v1.w + v2.w + v3.w;
    }
    for (; e < end; e++) {
        float4 v = h4[((size_t)csr[e] << c4shift) + t];
        acc.x += v.x; acc.y += v.y; acc.z += v.z; acc.w += v.w;
    }
    out[((size_t)node << c4shift) + t] = acc;
}

// ---------------- FP16 tensor-core GEMM: C = relu(A @ W + bias) ---------------
// R5 structure, m16n8k16 f16 (fp32 accumulate). A smem: half2[128][20]
// (16 k-pairs + pad; fragment loads hit all 32 banks). B smem: half2[16][136]
// (k-pair rows, residue-8 stride = R5's proven B pattern).
#define GBM 128
#define GBN 128
#define GBK 32
#define AST16 20
#define BST16 136

__global__ __launch_bounds__(256, 2)
void gemm_f16(const float* __restrict__ A,
              const float* __restrict__ W,      // K x N row-major
              const float* __restrict__ bias,   // N
              float* __restrict__ C,
              int M, int K, int N)
{
    __shared__ uint32_t As[GBM][AST16];   // half2: [row][k-pair]
    __shared__ uint32_t Bs[16][BST16];    // half2: [k-pair][col]

    int bm = blockIdx.x * GBM;
    int bn = blockIdx.y * GBN;
    int tid  = threadIdx.x;
    int wid  = tid >> 5;
    int lane = tid & 31;
    int grp  = lane >> 2;     // 0..7
    int tig  = lane & 3;      // 0..3
    int wm = (wid & 3) * 32;  // warp row offset in tile
    int wn = (wid >> 2) * 64; // warp col offset in tile

    float acc[2][8][4];
    #pragma unroll
    for (int i = 0; i < 2; i++)
        #pragma unroll
        for (int j = 0; j < 8; j++)
            #pragma unroll
            for (int r = 0; r < 4; r++) acc[i][j][r] = 0.f;

    float4 pa[4], pbe[2], pbo[2];

    auto ld_tiles = [&](int k0) {
        // A tile: 128 rows x 32 k = 1024 float4
        #pragma unroll
        for (int i = 0; i < 4; i++) {
            int li = tid + i * 256;
            int r  = li >> 3;          // 0..127
            int cq = (li & 7) * 4;     // 0..28
            int row = bm + r;
            pa[i] = (row < M) ? *(const float4*)(A + (size_t)row * K + k0 + cq)
                              : make_float4(0.f, 0.f, 0.f, 0.f);
        }
        // B tile: 32 k-rows x 128 cols, loaded as k-row PAIRS per thread
        #pragma unroll
        for (int i = 0; i < 2; i++) {
            int li = tid + i * 256;    // 0..511
            int kk = li >> 5;          // 0..15  (k-pair index)
            int nq = (li & 31) * 4;    // 0..124
            pbe[i] = *(const float4*)(W + (size_t)(k0 + 2 * kk) * N + bn + nq);
            pbo[i] = *(const float4*)(W + (size_t)(k0 + 2 * kk + 1) * N + bn + nq);
        }
    };

    auto st_tiles = [&]() {
        #pragma unroll
        for (int i = 0; i < 4; i++) {
            int li = tid + i * 256;
            int r   = li >> 3;
            int kk0 = (li & 7) * 2;    // k-pair base (0,2,...,14)
            As[r][kk0 + 0] = f2h2(pa[i].x, pa[i].y);
            As[r][kk0 + 1] = f2h2(pa[i].z, pa[i].w);
        }
        #pragma unroll
        for (int i = 0; i < 2; i++) {
            int li = tid + i * 256;
            int kk = li >> 5;
            int nq = (li & 31) * 4;
            Bs[kk][nq + 0] = f2h2(pbe[i].x, pbo[i].x);
            Bs[kk][nq + 1] = f2h2(pbe[i].y, pbo[i].y);
            Bs[kk][nq + 2] = f2h2(pbe[i].z, pbo[i].z);
            Bs[kk][nq + 3] = f2h2(pbe[i].w, pbo[i].w);
        }
    };

    ld_tiles(0);

    for (int k0 = 0; k0 < K; k0 += GBK) {
        st_tiles();
        __syncthreads();
        if (k0 + GBK < K) ld_tiles(k0 + GBK);   // hide LDG behind MMA phase

        // two K=16 slabs per 32-k chunk
        #pragma unroll
        for (int ks = 0; ks < 2; ks++) {
            int kkb = ks * 8;          // k-pair base of this slab
            uint32_t af[2][4];
            #pragma unroll
            for (int mt = 0; mt < 2; mt++) {
                int r0 = wm + mt * 16 + grp;
                af[mt][0] = As[r0][kkb + tig];
                af[mt][1] = As[r0 + 8][kkb + tig];
                af[mt][2] = As[r0][kkb + tig + 4];
                af[mt][3] = As[r0 + 8][kkb + tig + 4];
            }
            uint32_t bf[8][2];
            #pragma unroll
            for (int nt = 0; nt < 8; nt++) {
                int c0 = wn + nt * 8 + grp;
                bf[nt][0] = Bs[kkb + tig][c0];
                bf[nt][1] = Bs[kkb + tig + 4][c0];
            }
            #pragma unroll
            for (int mt = 0; mt < 2; mt++)
                #pragma unroll
                for (int nt = 0; nt < 8; nt++) {
                    asm volatile(
                        "mma.sync.aligned.m16n8k16.row.col.f32.f16.f16.f32 "
                        "{%0,%1,%2,%3}, {%4,%5,%6,%7}, {%8,%9}, {%0,%1,%2,%3};"
                        : "+f"(acc[mt][nt][0]), "+f"(acc[mt][nt][1]),
                          "+f"(acc[mt][nt][2]), "+f"(acc[mt][nt][3])
                        : "r"(af[mt][0]), "r"(af[mt][1]),
                          "r"(af[mt][2]), "r"(af[mt][3]),
                          "r"(bf[nt][0]), "r"(bf[nt][1]));
                }
        }
        __syncthreads();
    }

    // epilogue: bias + relu, float2 stores (same C layout as m16n8k8)
    #pragma unroll
    for (int mt = 0; mt < 2; mt++) {
        #pragma unroll
        for (int nt = 0; nt < 8; nt++) {
            int col = bn + wn + nt * 8 + 2 * tig;
            float b0 = bias[col], b1 = bias[col + 1];
            int r0 = bm + wm + mt * 16 + grp;
            if (r0 < M) {
                float2 c;
                c.x = fmaxf(acc[mt][nt][0] + b0, 0.f);
                c.y = fmaxf(acc[mt][nt][1] + b1, 0.f);
                *(float2*)(C + (size_t)r0 * N + col) = c;
            }
            if (r0 + 8 < M) {
                float2 c;
                c.x = fmaxf(acc[mt][nt][2] + b0, 0.f);
                c.y = fmaxf(acc[mt][nt][3] + b1, 0.f);
                *(float2*)(C + (size_t)(r0 + 8) * N + col) = c;
            }
        }
    }
}

// ---------------- pooling over sorted batch -----------------------------------
__global__ void graph_bounds(const void* __restrict__ batch,
                             const void* __restrict__ ei,
                             int* __restrict__ gstart) {
    int is64 = detect64(ei);
    int g = blockIdx.x * blockDim.x + threadIdx.x;
    if (g > N_GRAPHS) return;
    int lo = 0, hi = N_NODES;
    while (lo < hi) {
        int mid = (lo + hi) >> 1;
        if (idx_at(batch, mid, is64) < g) lo = mid + 1; else hi = mid;
    }
    gstart[g] = lo;
}

__global__ void pool_mean(const float* __restrict__ h,
                          const int* __restrict__ gstart,
                          float* __restrict__ pooled) {
    int g = blockIdx.x;
    int t = threadIdx.x;           // HID threads
    int beg = gstart[g], end = gstart[g + 1];
    float acc = 0.f;
    int n = beg;
    for (; n + 4 <= end; n += 4) {
        float a0 = h[(size_t)(n + 0) * HID + t];
        float a1 = h[(size_t)(n + 1) * HID + t];
        float a2 = h[(size_t)(n + 2) * HID + t];
        float a3 = h[(size_t)(n + 3) * HID + t];
        acc += a0 + a1 + a2 + a3;
    }
    for (; n < end; n++) acc += h[(size_t)n * HID + t];
    float c = fmaxf((float)(end - beg), 1.0f);
    pooled[(size_t)g * HID + t] = acc / c;
}

// ---------------- final MLP: out = relu(pooled@W1+b1)@W2+b2 ------------------
__global__ void final_mlp(const float* __restrict__ pooled,
                          const float* __restrict__ w1, const float* __restrict__ b1,
                          const float* __restrict__ w2, const float* __restrict__ b2,
                          float* __restrict__ out) {
    __shared__ float p[HID];
    __shared__ float hh[HID];
    int g = blockIdx.x;
    int t = threadIdx.x;

    p[t] = pooled[(size_t)g * HID + t];
    __syncthreads();

    float acc = b1[t];
    #pragma unroll 8
    for (int k = 0; k < HID; k++)
        acc += p[k] * w1[(size_t)k * HID + t];
    hh[t] = fmaxf(acc, 0.f);
    __syncthreads();

    int o  = t >> 4;
    int kk = t & 15;
    float s = 0.f;
    for (int k = kk; k < HID; k += 16)
        s += hh[k] * w2[(size_t)k * OUT_C + o];
    #pragma unroll
    for (int off = 8; off; off >>= 1)
        s += __shfl_xor_sync(0xffffffffu, s, off);
    if (kk == 0) out[(size_t)g * OUT_C + o] = s + b2[o];
}

// ---------------- launcher ----------------------------------------------------
extern "C" void kernel_launch(void* const* d_in, const int* in_sizes, int n_in,
                              void* d_out, int out_size)
{
    const float* x     = (const float*)d_in[0];
    const void*  ei    = d_in[1];
    const void*  batch = d_in[2];
    const float* w[16];
    for (int i = 0; i < 16; i++) w[i] = (const float*)d_in[3 + i];
    float* out = (float*)d_out;

    float *agg, *tmp, *h, *pool;
    int *deg, *ex, *bsums, *rowptr, *cursor, *csr, *gstart;
    cudaGetSymbolAddress((void**)&agg,    g_agg);
    cudaGetSymbolAddress((void**)&tmp,    g_tmp);
    cudaGetSymbolAddress((void**)&h,      g_h);
    cudaGetSymbolAddress((void**)&pool,   g_pool);
    cudaGetSymbolAddress((void**)&deg,    g_deg);
    cudaGetSymbolAddress((void**)&ex,     g_ex);
    cudaGetSymbolAddress((void**)&bsums,  g_bsums);
    cudaGetSymbolAddress((void**)&rowptr, g_rowptr);
    cudaGetSymbolAddress((void**)&cursor, g_cursor);
    cudaGetSymbolAddress((void**)&csr,    g_csr);
    cudaGetSymbolAddress((void**)&gstart, g_gstart);

    // ---- CSR build (once, reused by all 3 layers) ----
    cudaMemsetAsync(deg, 0, N_NODES * sizeof(int));
    deg_hist<<<(N_EDGES + 255) / 256, 256>>>(ei, deg);
    int nb = (N_NODES + SCAN_B - 1) / SCAN_B;   // 98
    scan1<<<nb, SCAN_B>>>(deg, ex, bsums);
    scan2<<<1, 128>>>(bsums, nb);
    scan3<<<(N_NODES + 256) / 256, 256>>>(ex, bsums, rowptr, cursor);
    csr_fill<<<(N_EDGES + 255) / 256, 256>>>(ei, cursor, csr);

    // ---- 3 GIN layers ----
    for (int layer = 0; layer < 3; layer++) {
        const float* hin = (layer == 0) ? x : h;
        int K = (layer == 0) ? IN_C : HID;
        int c4shift = (layer == 0) ? 5 : 6;
        int npb = 256 >> c4shift;

        aggregate4<<<(N_NODES + npb - 1) / npb, 256>>>(
            (const float4*)hin, rowptr, csr, (float4*)agg, c4shift);

        dim3 grid((N_NODES + GBM - 1) / GBM, HID / GBN);
        gemm_f16<<<grid, 256>>>(agg, w[layer * 4 + 0], w[layer * 4 + 1],
                                tmp, N_NODES, K, HID);
        gemm_f16<<<grid, 256>>>(tmp, w[layer * 4 + 2], w[layer * 4 + 3],
                                h, N_NODES, HID, HID);
    }

    // ---- pooling (batch is sorted) ----
    graph_bounds<<<3, 256>>>(batch, ei, gstart);
    pool_mean<<<N_GRAPHS, HID>>>(h, gstart, pool);

    final_mlp<<<N_GRAPHS, HID>>>(pool, w[12], w[13], w[14], w[15], out);
}

// round 17
// speedup vs baseline: 2.3844x; 1.1434x over previous
#include <cuda_runtime.h>
#include <cuda_bf16.h>
#include <cuda_fp16.h>
#include <cstdint>

#define N_NODES  50000
#define N_EDGES  800000
#define N_GRAPHS 512
#define IN_C     128
#define HID      256
#define OUT_C    16

// ---------------- scratch (static device globals; no allocation) -------------
__device__ __half g_agg [(size_t)N_NODES * HID];
__device__ __half g_tmp [(size_t)N_NODES * HID];
__device__ __half g_h   [(size_t)N_NODES * HID];
__device__ float  g_pool[N_GRAPHS * HID];
__device__ int    g_deg   [N_NODES];
__device__ int    g_ex    [N_NODES];
__device__ int    g_bsums [128];
__device__ int    g_rowptr[N_NODES + 1];
__device__ int    g_cursor[N_NODES];
__device__ int    g_csr   [N_EDGES];
__device__ int    g_gstart[N_GRAPHS + 1];

// ---------------- helpers -----------------------------------------------------
__device__ __forceinline__ int detect64(const void* ei) {
    const unsigned int* w = (const unsigned int*)ei;
    return ((w[1] | w[3] | w[5] | w[7]) == 0u) ? 1 : 0;
}
__device__ __forceinline__ int idx_at(const void* p, long long i, int is64) {
    if (is64) return (int)((const long long*)p)[i];
    return ((const int*)p)[i];
}
__device__ __forceinline__ uint32_t f2h2(float lo, float hi) {
    __half2 h = __floats2half2_rn(lo, hi);
    return *(uint32_t*)&h;
}
__device__ __forceinline__ void h8add(float* acc, uint4 v) {
    float2 a0 = __half22float2(*(__half2*)&v.x);
    float2 a1 = __half22float2(*(__half2*)&v.y);
    float2 a2 = __half22float2(*(__half2*)&v.z);
    float2 a3 = __half22float2(*(__half2*)&v.w);
    acc[0] += a0.x; acc[1] += a0.y; acc[2] += a1.x; acc[3] += a1.y;
    acc[4] += a2.x; acc[5] += a2.y; acc[6] += a3.x; acc[7] += a3.y;
}

// ---------------- CSR build (R5 form — measured best) --------------------------
__global__ void deg_hist(const void* __restrict__ ei, int* __restrict__ deg) {
    int is64 = detect64(ei);
    int e = blockIdx.x * blockDim.x + threadIdx.x;
    if (e >= N_EDGES) return;
    int d = idx_at(ei, (long long)N_EDGES + e, is64);
    atomicAdd(&deg[d], 1);
}

#define SCAN_B 512
__global__ void scan1(const int* __restrict__ deg, int* __restrict__ ex,
                      int* __restrict__ sums) {
    __shared__ int s[SCAN_B];
    int b = blockIdx.x, t = threadIdx.x;
    int i = b * SCAN_B + t;
    int v = (i < N_NODES) ? deg[i] : 0;
    s[t] = v; __syncthreads();
    for (int off = 1; off < SCAN_B; off <<= 1) {
        int x = (t >= off) ? s[t - off] : 0;
        __syncthreads();
        s[t] += x;
        __syncthreads();
    }
    if (i < N_NODES) ex[i] = s[t] - v;
    if (t == SCAN_B - 1) sums[b] = s[t];
}

__global__ void scan2(int* __restrict__ sums, int nb) {
    __shared__ int s[128];
    int t = threadIdx.x;
    int v = (t < nb) ? sums[t] : 0;
    s[t] = v; __syncthreads();
    for (int off = 1; off < 128; off <<= 1) {
        int x = (t >= off) ? s[t - off] : 0;
        __syncthreads();
        s[t] += x;
        __syncthreads();
    }
    if (t < nb) sums[t] = s[t] - v;
}

__global__ void scan3(const int* __restrict__ ex, const int* __restrict__ sums,
                      int* __restrict__ rowptr, int* __restrict__ cursor) {
    int i = blockIdx.x * blockDim.x + threadIdx.x;
    if (i < N_NODES) {
        int v = ex[i] + sums[i >> 9];
        rowptr[i] = v;
        cursor[i] = v;
    }
    if (i == 0) rowptr[N_NODES] = N_EDGES;
}

__global__ void csr_fill(const void* __restrict__ ei, int* __restrict__ cursor,
                         int* __restrict__ csr) {
    int is64 = detect64(ei);
    int e = blockIdx.x * blockDim.x + threadIdx.x;
    if (e >= N_EDGES) return;
    int s = idx_at(ei, e, is64);
    int d = idx_at(ei, (long long)N_EDGES + e, is64);
    int p = atomicAdd(&cursor[d], 1);
    csr[p] = s;
}

// ---------------- layer-0 aggregation: fp32 x in, fp16 out (C=128) ------------
// R5 gather structure (32 thr/node, float4 lanes); epilogue packs to half.
__global__ void aggregate_f32(const float4* __restrict__ h4,
                              const int* __restrict__ rowptr,
                              const int* __restrict__ csr,
                              __half* __restrict__ out) {
    int sub  = threadIdx.x >> 5;
    int t    = threadIdx.x & 31;
    int node = blockIdx.x * 8 + sub;
    if (node >= N_NODES) return;

    int beg = rowptr[node], end = rowptr[node + 1];
    float4 acc = h4[((size_t)node << 5) + t];
    int e = beg;
    for (; e + 4 <= end; e += 4) {
        int s0 = csr[e], s1 = csr[e + 1], s2 = csr[e + 2], s3 = csr[e + 3];
        float4 v0 = h4[((size_t)s0 << 5) + t];
        float4 v1 = h4[((size_t)s1 << 5) + t];
        float4 v2 = h4[((size_t)s2 << 5) + t];
        float4 v3 = h4[((size_t)s3 << 5) + t];
        acc.x += v0.x + v1.x + v2.x + v3.x;
        acc.y += v0.y + v1.y + v2.y + v3.y;
        acc.z += v0.z + v1.z + v2.z + v3.z;
        acc.w += v0.w + v1.w + v2.w + v3.w;
    }
    for (; e < end; e++) {
        float4 v = h4[((size_t)csr[e] << 5) + t];
        acc.x += v.x; acc.y += v.y; acc.z += v.z; acc.w += v.w;
    }
    uint2 o;
    o.x = f2h2(acc.x, acc.y);
    o.y = f2h2(acc.z, acc.w);
    *(uint2*)(out + ((size_t)node << 7) + t * 4) = o;
}

// ---------------- layers 1/2 aggregation: fp16 in/out (C=256) -----------------
// 32 thr/node, 8 halves (one uint4) per thread; fp32 accumulate.
__global__ void aggregate_f16(const uint4* __restrict__ h8,   // 32 uint4/node
                              const int* __restrict__ rowptr,
                              const int* __restrict__ csr,
                              uint4* __restrict__ out) {
    int sub  = threadIdx.x >> 5;
    int t    = threadIdx.x & 31;
    int node = blockIdx.x * 8 + sub;
    if (node >= N_NODES) return;

    const uint4* ht = h8 + t;
    float acc[8] = {};
    h8add(acc, ht[(size_t)node << 5]);

    int beg = rowptr[node], end = rowptr[node + 1];
    int e = beg;
    for (; e + 4 <= end; e += 4) {
        int s0 = csr[e], s1 = csr[e + 1], s2 = csr[e + 2], s3 = csr[e + 3];
        uint4 v0 = ht[(size_t)s0 << 5];
        uint4 v1 = ht[(size_t)s1 << 5];
        uint4 v2 = ht[(size_t)s2 << 5];
        uint4 v3 = ht[(size_t)s3 << 5];
        h8add(acc, v0); h8add(acc, v1); h8add(acc, v2); h8add(acc, v3);
    }
    for (; e < end; e++) h8add(acc, ht[(size_t)csr[e] << 5]);

    uint4 o;
    o.x = f2h2(acc[0], acc[1]);
    o.y = f2h2(acc[2], acc[3]);
    o.z = f2h2(acc[4], acc[5]);
    o.w = f2h2(acc[6], acc[7]);
    out[((size_t)node << 5) + t] = o;
}

// ---------------- FP16 tensor-core GEMM: C = relu(A @ W + bias) ---------------
// A: half [M][K] (pre-rounded). W: fp32 KxN. C: half [M][N].
// Same layout as R16: As half2[128][20], Bs half2[16][136].
#define GBM 128
#define GBN 128
#define GBK 32
#define AST16 20
#define BST16 136

__global__ __launch_bounds__(256, 2)
void gemm_f16(const __half* __restrict__ A,
              const float* __restrict__ W,      // K x N row-major
              const float* __restrict__ bias,   // N
              __half* __restrict__ C,
              int M, int K, int N)
{
    __shared__ uint32_t As[GBM][AST16];   // half2: [row][k-pair]
    __shared__ uint32_t Bs[16][BST16];    // half2: [k-pair][col]

    int bm = blockIdx.x * GBM;
    int bn = blockIdx.y * GBN;
    int tid  = threadIdx.x;
    int wid  = tid >> 5;
    int lane = tid & 31;
    int grp  = lane >> 2;     // 0..7
    int tig  = lane & 3;      // 0..3
    int wm = (wid & 3) * 32;  // warp row offset in tile
    int wn = (wid >> 2) * 64; // warp col offset in tile

    float acc[2][8][4];
    #pragma unroll
    for (int i = 0; i < 2; i++)
        #pragma unroll
        for (int j = 0; j < 8; j++)
            #pragma unroll
            for (int r = 0; r < 4; r++) acc[i][j][r] = 0.f;

    uint4 pa[2];
    float4 pbe[2], pbo[2];

    auto ld_tiles = [&](int k0) {
        // A tile: 128 rows x 32 halves = 512 uint4; 2 per thread
        #pragma unroll
        for (int i = 0; i < 2; i++) {
            int li = tid + i * 256;    // 0..511
            int r  = li >> 2;          // 0..127
            int kc = (li & 3) * 8;     // half index 0,8,16,24
            int row = bm + r;
            pa[i] = (row < M)
                ? *(const uint4*)(A + (size_t)row * K + k0 + kc)
                : make_uint4(0u, 0u, 0u, 0u);
        }
        // B tile: 32 k-rows x 128 cols, loaded as k-row PAIRS per thread
        #pragma unroll
        for (int i = 0; i < 2; i++) {
            int li = tid + i * 256;
            int kk = li >> 5;          // 0..15
            int nq = (li & 31) * 4;    // 0..124
            pbe[i] = *(const float4*)(W + (size_t)(k0 + 2 * kk) * N + bn + nq);
            pbo[i] = *(const float4*)(W + (size_t)(k0 + 2 * kk + 1) * N + bn + nq);
        }
    };

    auto st_tiles = [&]() {
        #pragma unroll
        for (int i = 0; i < 2; i++) {
            int li = tid + i * 256;
            int r  = li >> 2;
            int kc = (li & 3) * 8;     // k-pair base = kc/2 in {0,4,8,12}
            *(uint4*)&As[r][kc >> 1] = pa[i];   // raw halves, 16B aligned
        }
        #pragma unroll
        for (int i = 0; i < 2; i++) {
            int li = tid + i * 256;
            int kk = li >> 5;
            int nq = (li & 31) * 4;
            Bs[kk][nq + 0] = f2h2(pbe[i].x, pbo[i].x);
            Bs[kk][nq + 1] = f2h2(pbe[i].y, pbo[i].y);
            Bs[kk][nq + 2] = f2h2(pbe[i].z, pbo[i].z);
            Bs[kk][nq + 3] = f2h2(pbe[i].w, pbo[i].w);
        }
    };

    ld_tiles(0);

    for (int k0 = 0; k0 < K; k0 += GBK) {
        st_tiles();
        __syncthreads();
        if (k0 + GBK < K) ld_tiles(k0 + GBK);   // hide LDG behind MMA phase

        #pragma unroll
        for (int ks = 0; ks < 2; ks++) {
            int kkb = ks * 8;
            uint32_t af[2][4];
            #pragma unroll
            for (int mt = 0; mt < 2; mt++) {
                int r0 = wm + mt * 16 + grp;
                af[mt][0] = As[r0][kkb + tig];
                af[mt][1] = As[r0 + 8][kkb + tig];
                af[mt][2] = As[r0][kkb + tig + 4];
                af[mt][3] = As[r0 + 8][kkb + tig + 4];
            }
            uint32_t bf[8][2];
            #pragma unroll
            for (int nt = 0; nt < 8; nt++) {
                int c0 = wn + nt * 8 + grp;
                bf[nt][0] = Bs[kkb + tig][c0];
                bf[nt][1] = Bs[kkb + tig + 4][c0];
            }
            #pragma unroll
            for (int mt = 0; mt < 2; mt++)
                #pragma unroll
                for (int nt = 0; nt < 8; nt++) {
                    asm volatile(
                        "mma.sync.aligned.m16n8k16.row.col.f32.f16.f16.f32 "
                        "{%0,%1,%2,%3}, {%4,%5,%6,%7}, {%8,%9}, {%0,%1,%2,%3};"
                        : "+f"(acc[mt][nt][0]), "+f"(acc[mt][nt][1]),
                          "+f"(acc[mt][nt][2]), "+f"(acc[mt][nt][3])
                        : "r"(af[mt][0]), "r"(af[mt][1]),
                          "r"(af[mt][2]), "r"(af[mt][3]),
                          "r"(bf[nt][0]), "r"(bf[nt][1]));
                }
        }
        __syncthreads();
    }

    // epilogue: bias + relu, half2 stores
    #pragma unroll
    for (int mt = 0; mt < 2; mt++) {
        #pragma unroll
        for (int nt = 0; nt < 8; nt++) {
            int col = bn + wn + nt * 8 + 2 * tig;
            float b0 = bias[col], b1 = bias[col + 1];
            int r0 = bm + wm + mt * 16 + grp;
            if (r0 < M) {
                *(uint32_t*)(C + (size_t)r0 * N + col) =
                    f2h2(fmaxf(acc[mt][nt][0] + b0, 0.f),
                         fmaxf(acc[mt][nt][1] + b1, 0.f));
            }
            if (r0 + 8 < M) {
                *(uint32_t*)(C + (size_t)(r0 + 8) * N + col) =
                    f2h2(fmaxf(acc[mt][nt][2] + b0, 0.f),
                         fmaxf(acc[mt][nt][3] + b1, 0.f));
            }
        }
    }
}

// ---------------- pooling over sorted batch (h is fp16) -----------------------
__global__ void graph_bounds(const void* __restrict__ batch,
                             const void* __restrict__ ei,
                             int* __restrict__ gstart) {
    int is64 = detect64(ei);
    int g = blockIdx.x * blockDim.x + threadIdx.x;
    if (g > N_GRAPHS) return;
    int lo = 0, hi = N_NODES;
    while (lo < hi) {
        int mid = (lo + hi) >> 1;
        if (idx_at(batch, mid, is64) < g) lo = mid + 1; else hi = mid;
    }
    gstart[g] = lo;
}

__global__ void pool_mean(const __half* __restrict__ h,
                          const int* __restrict__ gstart,
                          float* __restrict__ pooled) {
    int g = blockIdx.x;
    int t = threadIdx.x;           // HID threads
    int beg = gstart[g], end = gstart[g + 1];
    float acc = 0.f;
    int n = beg;
    for (; n + 4 <= end; n += 4) {
        float a0 = __half2float(h[(size_t)(n + 0) * HID + t]);
        float a1 = __half2float(h[(size_t)(n + 1) * HID + t]);
        float a2 = __half2float(h[(size_t)(n + 2) * HID + t]);
        float a3 = __half2float(h[(size_t)(n + 3) * HID + t]);
        acc += a0 + a1 + a2 + a3;
    }
    for (; n < end; n++) acc += __half2float(h[(size_t)n * HID + t]);
    float c = fmaxf((float)(end - beg), 1.0f);
    pooled[(size_t)g * HID + t] = acc / c;
}

// ---------------- final MLP: out = relu(pooled@W1+b1)@W2+b2 ------------------
__global__ void final_mlp(const float* __restrict__ pooled,
                          const float* __restrict__ w1, const float* __restrict__ b1,
                          const float* __restrict__ w2, const float* __restrict__ b2,
                          float* __restrict__ out) {
    __shared__ float p[HID];
    __shared__ float hh[HID];
    int g = blockIdx.x;
    int t = threadIdx.x;

    p[t] = pooled[(size_t)g * HID + t];
    __syncthreads();

    float acc = b1[t];
    #pragma unroll 8
    for (int k = 0; k < HID; k++)
        acc += p[k] * w1[(size_t)k * HID + t];
    hh[t] = fmaxf(acc, 0.f);
    __syncthreads();

    int o  = t >> 4;
    int kk = t & 15;
    float s = 0.f;
    for (int k = kk; k < HID; k += 16)
        s += hh[k] * w2[(size_t)k * OUT_C + o];
    #pragma unroll
    for (int off = 8; off; off >>= 1)
        s += __shfl_xor_sync(0xffffffffu, s, off);
    if (kk == 0) out[(size_t)g * OUT_C + o] = s + b2[o];
}

// ---------------- launcher ----------------------------------------------------
extern "C" void kernel_launch(void* const* d_in, const int* in_sizes, int n_in,
                              void* d_out, int out_size)
{
    const float* x     = (const float*)d_in[0];
    const void*  ei    = d_in[1];
    const void*  batch = d_in[2];
    const float* w[16];
    for (int i = 0; i < 16; i++) w[i] = (const float*)d_in[3 + i];
    float* out = (float*)d_out;

    __half *agg, *tmp, *h;
    float *pool;
    int *deg, *ex, *bsums, *rowptr, *cursor, *csr, *gstart;
    cudaGetSymbolAddress((void**)&agg,    g_agg);
    cudaGetSymbolAddress((void**)&tmp,    g_tmp);
    cudaGetSymbolAddress((void**)&h,      g_h);
    cudaGetSymbolAddress((void**)&pool,   g_pool);
    cudaGetSymbolAddress((void**)&deg,    g_deg);
    cudaGetSymbolAddress((void**)&ex,     g_ex);
    cudaGetSymbolAddress((void**)&bsums,  g_bsums);
    cudaGetSymbolAddress((void**)&rowptr, g_rowptr);
    cudaGetSymbolAddress((void**)&cursor, g_cursor);
    cudaGetSymbolAddress((void**)&csr,    g_csr);
    cudaGetSymbolAddress((void**)&gstart, g_gstart);

    // ---- CSR build (once, reused by all 3 layers) ----
    cudaMemsetAsync(deg, 0, N_NODES * sizeof(int));
    deg_hist<<<(N_EDGES + 255) / 256, 256>>>(ei, deg);
    int nb = (N_NODES + SCAN_B - 1) / SCAN_B;   // 98
    scan1<<<nb, SCAN_B>>>(deg, ex, bsums);
    scan2<<<1, 128>>>(bsums, nb);
    scan3<<<(N_NODES + 256) / 256, 256>>>(ex, bsums, rowptr, cursor);
    csr_fill<<<(N_EDGES + 255) / 256, 256>>>(ei, cursor, csr);

    int nblocks = (N_NODES + 7) / 8;   // 8 nodes per 256-thread block

    // ---- 3 GIN layers ----
    for (int layer = 0; layer < 3; layer++) {
        int K = (layer == 0) ? IN_C : HID;

        if (layer == 0)
            aggregate_f32<<<nblocks, 256>>>((const float4*)x, rowptr, csr, agg);
        else
            aggregate_f16<<<nblocks, 256>>>((const uint4*)h, rowptr, csr,
                                            (uint4*)agg);

        dim3 grid((N_NODES + GBM - 1) / GBM, HID / GBN);
        gemm_f16<<<grid, 256>>>(agg, w[layer * 4 + 0], w[layer * 4 + 1],
                                tmp, N_NODES, K, HID);
        gemm_f16<<<grid, 256>>>(tmp, w[layer * 4 + 2], w[layer * 4 + 3],
                                h, N_NODES, HID, HID);
    }

    // ---- pooling (batch is sorted) ----
    graph_bounds<<<3, 256>>>(batch, ei, gstart);
    pool_mean<<<N_GRAPHS, HID>>>(h, gstart, pool);

    final_mlp<<<N_GRAPHS, HID>>>(pool, w[12], w[13], w[14], w[15], out);
}